// round 9
// baseline (speedup 1.0000x reference)
#include <cuda_runtime.h>

#define N_NODES 100000
#define N_EDGES 1600000
#define NB_SCAN 98              // ceil((N_NODES+1)/1024)
#define NEG_SLOPE 0.2f
#define FULLM 0xffffffffu
#define GB_GEMM 1563            // ceil(N_NODES/64)
#define GB_HIST 6250            // ceil(N_EDGES/256)

// ---------------- scratch (device globals; zero-initialized at module load) ----------
// Cross-call invariant: g_deg and g_tstat are zero at the start of every
// kernel_launch call — module-load zero-init covers the first call; k_fill
// re-zeroes them (after their last use) for every later call.
__device__ int      g_deg[N_NODES + 1];
__device__ int      g_rowptr[N_NODES + 1];
__device__ int      g_ord[N_EDGES];       // within-dst-bucket rank of each edge
__device__ unsigned g_tstat[NB_SCAN];     // lookback status: [31:30] flag (1=agg,2=prefix), [29:0] value
__device__ int      g_adj[N_EDGES];       // src indices in CSR (dst-grouped) order
__device__ float    g_ex[N_EDGES];        // exp(leakyrelu(logit)) per edge, CSR order
__device__ float    g_h[N_NODES * 64];    // transformed features of current layer
__device__ float    g_feat[N_NODES * 64]; // layer-1 output (input to layer 2)
__device__ float    g_as[N_NODES];
__device__ float    g_ad[N_NODES];

// ---------------- smem-staged SIMT outer-product GEMM + attention logits -------------
// Block = 256 threads -> tile of 64 nodes x 64 outputs. Thread (tx=tid&15,
// ty=tid>>4) owns a 4x4 register tile: nodes tx*4..+3, outs ty*4..+3.
// X tile and W are transposed into k-major smem; inner loop per k is
// 2x LDS.128 (conflict-light) + 16 FFMA -> FFMA-pipe bound.
// HIST: blocks >= GB_GEMM run the dst-degree histogram + bucket-rank capture
// (LSU/atomic-bound, overlaps the FMA-bound gemm blocks for ~free). The
// atomicAdd return value IS the edge's rank within its dst bucket, which
// makes k_fill atomic-free.
template <int IN, bool HIST>
__global__ void __launch_bounds__(256)
k_gemm(const float* __restrict__ Xext,
       const float* __restrict__ W,
       const float* __restrict__ avsrc,
       const float* __restrict__ avdst,
       const int* __restrict__ ei,
       float* __restrict__ out) {
    if (HIST && blockIdx.x >= GB_GEMM) {
        int e = (blockIdx.x - GB_GEMM) * 256 + threadIdx.x;
        if (e < N_EDGES) {
            int d = __ldg(&ei[N_EDGES + e]);
            g_ord[e] = atomicAdd(&g_deg[d + 1], 1);
        }
        return;
    }
    __shared__ float xs[64][68];     // xs[k][node]
    __shared__ float ws[64][68];     // ws[k][out]
    __shared__ float sASP[64][17];   // per-node logit partials over ty
    __shared__ float sADP[64][17];

    const float* X = (IN == 128) ? Xext : (const float*)g_feat;
    const int tid = threadIdx.x;
    const int tx  = tid & 15;
    const int ty  = tid >> 4;
    const int nbase = blockIdx.x * 64;
    const int C = IN / 4;            // float4s per row

    if (!HIST && blockIdx.x == 0 && tid < 64) out[tid] = 0.0f;

    const float4* X4 = (const float4*)X;
    const float4* W4 = (const float4*)W;

    float acc[4][4];
#pragma unroll
    for (int i = 0; i < 4; i++)
#pragma unroll
        for (int o = 0; o < 4; o++) acc[i][o] = 0.f;

#pragma unroll
    for (int ch = 0; ch < IN / 64; ch++) {
        const int kc4 = ch * 16;     // float4 column offset of this k-chunk
        __syncthreads();
        // stage X-tile and W chunk, transposing to k-major.
        // idx bits: [1:0]->c4 low, [7:2]->row, [9:8]->c4 high
        // -> warp covers 8 rows x 4 c4: 64B-coalesced global reads, 2-way STS banks.
#pragma unroll
        for (int it = 0; it < 4; it++) {
            int idx = tid + it * 256;
            int c4  = (idx & 3) | (((idx >> 8) & 3) << 2);
            int r   = (idx >> 2) & 63;
            int xrow = min(nbase + r, N_NODES - 1);     // clamp tail (stores guarded)
            float4 v = __ldg(&X4[(long)xrow * C + kc4 + c4]);
            xs[c4 * 4 + 0][r] = v.x; xs[c4 * 4 + 1][r] = v.y;
            xs[c4 * 4 + 2][r] = v.z; xs[c4 * 4 + 3][r] = v.w;
            float4 wv = __ldg(&W4[(long)r * C + kc4 + c4]);
            ws[c4 * 4 + 0][r] = wv.x; ws[c4 * 4 + 1][r] = wv.y;
            ws[c4 * 4 + 2][r] = wv.z; ws[c4 * 4 + 3][r] = wv.w;
        }
        __syncthreads();

#pragma unroll 4
        for (int kk = 0; kk < 64; kk++) {
            float4 xv = *(const float4*)&xs[kk][tx * 4];   // 4 nodes at this k
            float4 wv = *(const float4*)&ws[kk][ty * 4];   // 4 outs at this k
            acc[0][0] += xv.x * wv.x; acc[0][1] += xv.x * wv.y;
            acc[0][2] += xv.x * wv.z; acc[0][3] += xv.x * wv.w;
            acc[1][0] += xv.y * wv.x; acc[1][1] += xv.y * wv.y;
            acc[1][2] += xv.y * wv.z; acc[1][3] += xv.y * wv.w;
            acc[2][0] += xv.z * wv.x; acc[2][1] += xv.z * wv.y;
            acc[2][2] += xv.z * wv.z; acc[2][3] += xv.z * wv.w;
            acc[3][0] += xv.w * wv.x; acc[3][1] += xv.w * wv.y;
            acc[3][2] += xv.w * wv.z; acc[3][3] += xv.w * wv.w;
        }
    }

    // store h
    float4* H4 = (float4*)g_h;
#pragma unroll
    for (int i = 0; i < 4; i++) {
        int node = nbase + tx * 4 + i;
        if (node < N_NODES)
            H4[(long)node * 16 + ty] =
                make_float4(acc[i][0], acc[i][1], acc[i][2], acc[i][3]);
    }

    // attention logit partials: as = h . a_src, ad = h . a_dst (deterministic tree)
    float4 sv = __ldg((const float4*)avsrc + ty);
    float4 dv = __ldg((const float4*)avdst + ty);
#pragma unroll
    for (int i = 0; i < 4; i++) {
        float sp = acc[i][0] * sv.x + acc[i][1] * sv.y + acc[i][2] * sv.z + acc[i][3] * sv.w;
        float dp = acc[i][0] * dv.x + acc[i][1] * dv.y + acc[i][2] * dv.z + acc[i][3] * dv.w;
        sASP[tx * 4 + i][ty] = sp;
        sADP[tx * 4 + i][ty] = dp;
    }
    __syncthreads();
    if (tid < 64) {
        int node = nbase + tid;
        if (node < N_NODES) {
            float s = 0.f, d = 0.f;
#pragma unroll
            for (int j = 0; j < 16; j++) { s += sASP[tid][j]; d += sADP[tid][j]; }
            g_as[node] = s;
            g_ad[node] = d;
        }
    }
}

// ---------------- single-kernel decoupled-lookback scan of g_deg -> g_rowptr ----------
// 98 tiles of 1024; 98 blocks co-resident so polling always makes progress.
// Status word packs flag+value so the single 32-bit atomic publish needs no fence.
__global__ void __launch_bounds__(1024) k_scan() {
    __shared__ int s[1024];
    __shared__ int s_prefix;
    const int t = threadIdx.x;
    const int tile = blockIdx.x;
    const int i = tile * 1024 + t;
    int v = (i <= N_NODES) ? g_deg[i] : 0;
    s[t] = v;
    __syncthreads();
    for (int off = 1; off < 1024; off <<= 1) {
        int x = (t >= off) ? s[t - off] : 0;
        __syncthreads();
        s[t] += x;
        __syncthreads();
    }
    const int inc = s[t];
    const int total = s[1023];

    if (t == 0) {
        if (tile == 0) {
            atomicExch(&g_tstat[0], (2u << 30) | (unsigned)total);
            s_prefix = 0;
        } else {
            atomicExch(&g_tstat[tile], (1u << 30) | (unsigned)total);
            int prefix = 0;
            int p = tile - 1;
            while (true) {
                unsigned st = *(volatile unsigned*)&g_tstat[p];
                unsigned f = st >> 30;
                if (f == 0u) continue;
                prefix += (int)(st & 0x3FFFFFFFu);
                if (f == 2u) break;
                p--;
            }
            atomicExch(&g_tstat[tile], (2u << 30) | (unsigned)(prefix + total));
            s_prefix = prefix;
        }
    }
    __syncthreads();
    const int val = inc + s_prefix;
    if (i <= N_NODES) g_rowptr[i] = val;
}

// ---------------- atomic-free adjacency fill + layer-1 edge-exp + cleanup -----------
// pos = rowptr[dst] + precomputed bucket rank. Also precomputes the layer-1
// per-edge softmax numerator ex = exp(leakyrelu(as[src]+ad[dst])) into CSR
// order, so k_agg's inner loop needs only coalesced loads (the scattered
// as[src] read happens here, in a latency-insensitive throughput kernel).
__global__ void __launch_bounds__(512) k_fill(const int* __restrict__ ei) {
    int gid = blockIdx.x * 512 + threadIdx.x;
    if (gid <= N_NODES) g_deg[gid] = 0;       // reset for next kernel_launch call
    if (gid < NB_SCAN) g_tstat[gid] = 0u;     // reset lookback status
    if (gid < N_EDGES) {
        int srcv = __ldg(&ei[gid]);
        int d    = __ldg(&ei[N_EDGES + gid]);
        int pos  = __ldg(&g_rowptr[d]) + g_ord[gid];
        g_adj[pos] = srcv;
        float e = __ldg(&g_as[srcv]) + __ldg(&g_ad[d]);
        e = (e > 0.f) ? e : NEG_SLOPE * e;
        g_ex[pos] = __expf(e);
    }
}

// ---------------- layer-2 edge-exp (same addressing as k_fill, after gemm2) ---------
__global__ void __launch_bounds__(512) k_ex(const int* __restrict__ ei) {
    int e = blockIdx.x * 512 + threadIdx.x;
    if (e < N_EDGES) {
        int srcv = __ldg(&ei[e]);
        int d    = __ldg(&ei[N_EDGES + e]);
        int pos  = __ldg(&g_rowptr[d]) + g_ord[e];
        float v = __ldg(&g_as[srcv]) + __ldg(&g_ad[d]);
        v = (v > 0.f) ? v : NEG_SLOPE * v;
        g_ex[pos] = __expf(v);
    }
}

// ---------------- half-warp-per-node softmax aggregation (atomic-free) ---------------
// 16 lanes own one node; lane l holds features [4l, 4l+4). One LDG.128 across
// the 16 lanes fetches a full 256B h-row per edge; gathers batched 4-wide
// (8 LDG.128 in flight per warp). Per-edge exp values are precomputed in CSR
// order (k_fill / k_ex), so the chunk prologue is two coalesced loads — no
// scattered dependent load, no expf, in the critical chain.
// exp-max subtraction omitted: logits are O(10) so fp32 exp cannot overflow
// and the softmax ratio is unchanged.
// mode 1: relu + store g_feat; mode 2: fused global mean pool into out.
__global__ void __launch_bounds__(512)
k_agg(const float* __restrict__ b, float* __restrict__ out, int mode) {
    __shared__ float sred[64];
    if (mode == 2) {
        if (threadIdx.x < 64) sred[threadIdx.x] = 0.f;
        __syncthreads();
    }
    const int lane = threadIdx.x & 31;
    const int l = lane & 15;
    const unsigned hm = 0xFFFFu << (lane & 16);
    const int node = (blockIdx.x * 512 + threadIdx.x) >> 4;   // exact: 3125*512/16 = 100000

    const float4* H4 = (const float4*)g_h;
    float e0 = g_as[node] + g_ad[node];
    e0 = (e0 > 0.f) ? e0 : NEG_SLOPE * e0;
    const float exs = __expf(e0);                 // self-loop term

    float4 hv = __ldg(H4 + (long)node * 16 + l);
    float4 acc = make_float4(exs * hv.x, exs * hv.y, exs * hv.z, exs * hv.w);
    float dsum = 0.f;

    const int beg = __ldg(&g_rowptr[node]);
    const int end = __ldg(&g_rowptr[node + 1]);
    for (int k = beg; k < end; k += 16) {
        int idx = k + l;
        int s = 0;
        float ex = 0.f;
        if (idx < end) {
            s  = __ldg(&g_adj[idx]);
            ex = __ldg(&g_ex[idx]);
        }
        dsum += ex;
        const int cnt = min(16, end - k);
        int j = 0;
        for (; j + 4 <= cnt; j += 4) {
            int   s0 = __shfl_sync(hm, s, j, 16);
            int   s1 = __shfl_sync(hm, s, j + 1, 16);
            int   s2 = __shfl_sync(hm, s, j + 2, 16);
            int   s3 = __shfl_sync(hm, s, j + 3, 16);
            float x0 = __shfl_sync(hm, ex, j, 16);
            float x1 = __shfl_sync(hm, ex, j + 1, 16);
            float x2 = __shfl_sync(hm, ex, j + 2, 16);
            float x3 = __shfl_sync(hm, ex, j + 3, 16);
            float4 h0 = __ldg(H4 + (long)s0 * 16 + l);
            float4 h1 = __ldg(H4 + (long)s1 * 16 + l);
            float4 h2 = __ldg(H4 + (long)s2 * 16 + l);
            float4 h3 = __ldg(H4 + (long)s3 * 16 + l);
            acc.x += x0 * h0.x; acc.y += x0 * h0.y; acc.z += x0 * h0.z; acc.w += x0 * h0.w;
            acc.x += x1 * h1.x; acc.y += x1 * h1.y; acc.z += x1 * h1.z; acc.w += x1 * h1.w;
            acc.x += x2 * h2.x; acc.y += x2 * h2.y; acc.z += x2 * h2.z; acc.w += x2 * h2.w;
            acc.x += x3 * h3.x; acc.y += x3 * h3.y; acc.z += x3 * h3.z; acc.w += x3 * h3.w;
        }
        for (; j < cnt; j++) {
            int   sj = __shfl_sync(hm, s, j, 16);
            float xj = __shfl_sync(hm, ex, j, 16);
            float4 hj = __ldg(H4 + (long)sj * 16 + l);
            acc.x += xj * hj.x; acc.y += xj * hj.y; acc.z += xj * hj.z; acc.w += xj * hj.w;
        }
    }
#pragma unroll
    for (int m = 8; m; m >>= 1) dsum += __shfl_xor_sync(hm, dsum, m, 16);

    const float inv = 1.0f / (dsum + exs);
    float4 bb = __ldg((const float4*)b + l);
    float4 r = make_float4(acc.x * inv + bb.x, acc.y * inv + bb.y,
                           acc.z * inv + bb.z, acc.w * inv + bb.w);

    if (mode == 1) {
        r.x = fmaxf(r.x, 0.f); r.y = fmaxf(r.y, 0.f);
        r.z = fmaxf(r.z, 0.f); r.w = fmaxf(r.w, 0.f);
        ((float4*)g_feat)[(long)node * 16 + l] = r;
    } else {
        // fused global mean pool
        __syncwarp(FULLM);
        r.x += __shfl_xor_sync(FULLM, r.x, 16);
        r.y += __shfl_xor_sync(FULLM, r.y, 16);
        r.z += __shfl_xor_sync(FULLM, r.z, 16);
        r.w += __shfl_xor_sync(FULLM, r.w, 16);
        if (lane < 16) {
            atomicAdd(&sred[4 * l + 0], r.x);
            atomicAdd(&sred[4 * l + 1], r.y);
            atomicAdd(&sred[4 * l + 2], r.z);
            atomicAdd(&sred[4 * l + 3], r.w);
        }
        __syncthreads();
        if (threadIdx.x < 64)
            atomicAdd(&out[threadIdx.x], sred[threadIdx.x] * (1.0f / N_NODES));
    }
}

// ---------------- launch ----------------
extern "C" void kernel_launch(void* const* d_in, const int* in_sizes, int n_in,
                              void* d_out, int out_size) {
    const float* x   = (const float*)d_in[0];
    const int*   ei  = (const int*)d_in[1];
    // d_in[2] = edge_attr (unused; GATConv edge_dim=None)
    const float* W1  = (const float*)d_in[3];
    const float* as1 = (const float*)d_in[4];
    const float* ad1 = (const float*)d_in[5];
    const float* b1  = (const float*)d_in[6];
    const float* W2  = (const float*)d_in[7];
    const float* as2 = (const float*)d_in[8];
    const float* ad2 = (const float*)d_in[9];
    const float* b2  = (const float*)d_in[10];
    float* out = (float*)d_out;

    // (0) layer-1 gemm + dst histogram/rank capture (fused, complementary pipes)
    k_gemm<128, true><<<GB_GEMM + GB_HIST, 256>>>(x, W1, as1, ad1, ei, out);
    // (1) rowptr via single-kernel decoupled lookback scan
    k_scan<<<NB_SCAN, 1024>>>();
    // (2) atomic-free adjacency fill + layer-1 edge-exp + scratch reset
    k_fill<<<3125, 512>>>(ei);
    // (3) layer-1 aggregation
    k_agg<<<3125, 512>>>(b1, out, 1);
    // (4) layer-2 gemm (+ zero out)
    k_gemm<64, false><<<GB_GEMM, 256>>>(nullptr, W2, as2, ad2, nullptr, out);
    // (5) layer-2 edge-exp
    k_ex<<<3125, 512>>>(ei);
    // (6) layer-2 aggregation + fused global mean pool
    k_agg<<<3125, 512>>>(b2, out, 2);
}

// round 10
// speedup vs baseline: 1.2374x; 1.2374x over previous
#include <cuda_runtime.h>

#define N_NODES 100000
#define N_EDGES 1600000
#define NB_SCAN 98              // ceil((N_NODES+1)/1024)
#define NEG_SLOPE 0.2f
#define FULLM 0xffffffffu
#define GB_GEMM 1563            // ceil(N_NODES/64)
#define GB_HIST 6250            // ceil(N_EDGES/256)

// ---------------- scratch (device globals; zero-initialized at module load) ----------
// Cross-call invariant: g_deg and g_tstat are zero at the start of every
// kernel_launch call — module-load zero-init covers the first call; k_fill
// re-zeroes them (after their last use) for every later call.
__device__ int      g_deg[N_NODES + 1];
__device__ int      g_rowptr[N_NODES + 1];
__device__ int      g_ord[N_EDGES];       // within-dst-bucket rank of each edge
__device__ unsigned g_tstat[NB_SCAN];     // lookback status: [31:30] flag (1=agg,2=prefix), [29:0] value
__device__ int      g_adj[N_EDGES];       // src indices in CSR (dst-grouped) order
__device__ float    g_h[N_NODES * 64];    // transformed features of current layer
__device__ float    g_feat[N_NODES * 64]; // layer-1 output (input to layer 2)
__device__ float    g_as[N_NODES];
__device__ float    g_ad[N_NODES];

// ---------------- smem-staged SIMT outer-product GEMM + attention logits -------------
// Block = 256 threads -> tile of 64 nodes x 64 outputs. Thread (tx=tid&15,
// ty=tid>>4) owns a 4x4 register tile: nodes tx*4..+3, outs ty*4..+3.
// X tile and W are transposed into k-major smem; inner loop per k is
// 2x LDS.128 (conflict-light) + 16 FFMA -> FFMA-pipe bound.
// HIST: blocks >= GB_GEMM run the dst-degree histogram + bucket-rank capture
// (LSU/atomic-bound, overlaps the FMA-bound gemm blocks for ~free). The
// atomicAdd return value IS the edge's rank within its dst bucket, which
// makes k_fill atomic-free.
template <int IN, bool HIST>
__global__ void __launch_bounds__(256)
k_gemm(const float* __restrict__ Xext,
       const float* __restrict__ W,
       const float* __restrict__ avsrc,
       const float* __restrict__ avdst,
       const int* __restrict__ ei,
       float* __restrict__ out) {
    if (HIST && blockIdx.x >= GB_GEMM) {
        int e = (blockIdx.x - GB_GEMM) * 256 + threadIdx.x;
        if (e < N_EDGES) {
            int d = __ldg(&ei[N_EDGES + e]);
            g_ord[e] = atomicAdd(&g_deg[d + 1], 1);
        }
        return;
    }
    __shared__ float xs[64][68];     // xs[k][node]
    __shared__ float ws[64][68];     // ws[k][out]
    __shared__ float sASP[64][17];   // per-node logit partials over ty
    __shared__ float sADP[64][17];

    const float* X = (IN == 128) ? Xext : (const float*)g_feat;
    const int tid = threadIdx.x;
    const int tx  = tid & 15;
    const int ty  = tid >> 4;
    const int nbase = blockIdx.x * 64;
    const int C = IN / 4;            // float4s per row

    if (!HIST && blockIdx.x == 0 && tid < 64) out[tid] = 0.0f;

    const float4* X4 = (const float4*)X;
    const float4* W4 = (const float4*)W;

    float acc[4][4];
#pragma unroll
    for (int i = 0; i < 4; i++)
#pragma unroll
        for (int o = 0; o < 4; o++) acc[i][o] = 0.f;

#pragma unroll
    for (int ch = 0; ch < IN / 64; ch++) {
        const int kc4 = ch * 16;     // float4 column offset of this k-chunk
        __syncthreads();
        // stage X-tile and W chunk, transposing to k-major.
        // idx bits: [1:0]->c4 low, [7:2]->row, [9:8]->c4 high
        // -> warp covers 8 rows x 4 c4: 64B-coalesced global reads, 2-way STS banks.
#pragma unroll
        for (int it = 0; it < 4; it++) {
            int idx = tid + it * 256;
            int c4  = (idx & 3) | (((idx >> 8) & 3) << 2);
            int r   = (idx >> 2) & 63;
            int xrow = min(nbase + r, N_NODES - 1);     // clamp tail (stores guarded)
            float4 v = __ldg(&X4[(long)xrow * C + kc4 + c4]);
            xs[c4 * 4 + 0][r] = v.x; xs[c4 * 4 + 1][r] = v.y;
            xs[c4 * 4 + 2][r] = v.z; xs[c4 * 4 + 3][r] = v.w;
            float4 wv = __ldg(&W4[(long)r * C + kc4 + c4]);
            ws[c4 * 4 + 0][r] = wv.x; ws[c4 * 4 + 1][r] = wv.y;
            ws[c4 * 4 + 2][r] = wv.z; ws[c4 * 4 + 3][r] = wv.w;
        }
        __syncthreads();

#pragma unroll 4
        for (int kk = 0; kk < 64; kk++) {
            float4 xv = *(const float4*)&xs[kk][tx * 4];   // 4 nodes at this k
            float4 wv = *(const float4*)&ws[kk][ty * 4];   // 4 outs at this k
            acc[0][0] += xv.x * wv.x; acc[0][1] += xv.x * wv.y;
            acc[0][2] += xv.x * wv.z; acc[0][3] += xv.x * wv.w;
            acc[1][0] += xv.y * wv.x; acc[1][1] += xv.y * wv.y;
            acc[1][2] += xv.y * wv.z; acc[1][3] += xv.y * wv.w;
            acc[2][0] += xv.z * wv.x; acc[2][1] += xv.z * wv.y;
            acc[2][2] += xv.z * wv.z; acc[2][3] += xv.z * wv.w;
            acc[3][0] += xv.w * wv.x; acc[3][1] += xv.w * wv.y;
            acc[3][2] += xv.w * wv.z; acc[3][3] += xv.w * wv.w;
        }
    }

    // store h
    float4* H4 = (float4*)g_h;
#pragma unroll
    for (int i = 0; i < 4; i++) {
        int node = nbase + tx * 4 + i;
        if (node < N_NODES)
            H4[(long)node * 16 + ty] =
                make_float4(acc[i][0], acc[i][1], acc[i][2], acc[i][3]);
    }

    // attention logit partials: as = h . a_src, ad = h . a_dst (deterministic tree)
    float4 sv = __ldg((const float4*)avsrc + ty);
    float4 dv = __ldg((const float4*)avdst + ty);
#pragma unroll
    for (int i = 0; i < 4; i++) {
        float sp = acc[i][0] * sv.x + acc[i][1] * sv.y + acc[i][2] * sv.z + acc[i][3] * sv.w;
        float dp = acc[i][0] * dv.x + acc[i][1] * dv.y + acc[i][2] * dv.z + acc[i][3] * dv.w;
        sASP[tx * 4 + i][ty] = sp;
        sADP[tx * 4 + i][ty] = dp;
    }
    __syncthreads();
    if (tid < 64) {
        int node = nbase + tid;
        if (node < N_NODES) {
            float s = 0.f, d = 0.f;
#pragma unroll
            for (int j = 0; j < 16; j++) { s += sASP[tid][j]; d += sADP[tid][j]; }
            g_as[node] = s;
            g_ad[node] = d;
        }
    }
}

// ---------------- single-kernel decoupled-lookback scan of g_deg -> g_rowptr ----------
// 98 tiles of 1024; 98 blocks co-resident so polling always makes progress.
// Status word packs flag+value so the single 32-bit atomic publish needs no fence.
__global__ void __launch_bounds__(1024) k_scan() {
    __shared__ int s[1024];
    __shared__ int s_prefix;
    const int t = threadIdx.x;
    const int tile = blockIdx.x;
    const int i = tile * 1024 + t;
    int v = (i <= N_NODES) ? g_deg[i] : 0;
    s[t] = v;
    __syncthreads();
    for (int off = 1; off < 1024; off <<= 1) {
        int x = (t >= off) ? s[t - off] : 0;
        __syncthreads();
        s[t] += x;
        __syncthreads();
    }
    const int inc = s[t];
    const int total = s[1023];

    if (t == 0) {
        if (tile == 0) {
            atomicExch(&g_tstat[0], (2u << 30) | (unsigned)total);
            s_prefix = 0;
        } else {
            atomicExch(&g_tstat[tile], (1u << 30) | (unsigned)total);
            int prefix = 0;
            int p = tile - 1;
            while (true) {
                unsigned st = *(volatile unsigned*)&g_tstat[p];
                unsigned f = st >> 30;
                if (f == 0u) continue;
                prefix += (int)(st & 0x3FFFFFFFu);
                if (f == 2u) break;
                p--;
            }
            atomicExch(&g_tstat[tile], (2u << 30) | (unsigned)(prefix + total));
            s_prefix = prefix;
        }
    }
    __syncthreads();
    const int val = inc + s_prefix;
    if (i <= N_NODES) g_rowptr[i] = val;
}

// ---------------- atomic-free adjacency fill + cleanup for next call ----------------
// pos = rowptr[dst] + precomputed bucket rank: loads + one scattered store only.
__global__ void __launch_bounds__(512) k_fill(const int* __restrict__ ei) {
    int gid = blockIdx.x * 512 + threadIdx.x;
    if (gid <= N_NODES) g_deg[gid] = 0;       // reset for next kernel_launch call
    if (gid < NB_SCAN) g_tstat[gid] = 0u;     // reset lookback status
    if (gid < N_EDGES) {
        int d   = __ldg(&ei[N_EDGES + gid]);
        int pos = __ldg(&g_rowptr[d]) + g_ord[gid];
        g_adj[pos] = __ldg(&ei[gid]);
    }
}

// ---------------- half-warp-per-node softmax aggregation (atomic-free) ---------------
// 16 lanes own one node; lane l holds features [4l, 4l+4). One LDG.128 across
// the 16 lanes fetches a full 256B h-row per edge. The gather loop is a single
// predicated 4-wide batch: invalid tail slots carry (s=0, ex=0) so they gather
// h[0] with zero weight — tail edges keep MLP 4 instead of falling into a
// serial per-edge path (which covered ~half of all edges at mean degree 17).
// exp-max subtraction omitted: logits are O(10) so fp32 exp cannot overflow
// and the softmax ratio is unchanged.
// mode 1: relu + store g_feat; mode 2: fused global mean pool into out.
__global__ void __launch_bounds__(512)
k_agg(const float* __restrict__ b, float* __restrict__ out, int mode) {
    __shared__ float sred[64];
    if (mode == 2) {
        if (threadIdx.x < 64) sred[threadIdx.x] = 0.f;
        __syncthreads();
    }
    const int lane = threadIdx.x & 31;
    const int l = lane & 15;
    const unsigned hm = 0xFFFFu << (lane & 16);
    const int node = (blockIdx.x * 512 + threadIdx.x) >> 4;   // exact: 3125*512/16 = 100000

    const float4* H4 = (const float4*)g_h;
    const float adn = g_ad[node];
    float e0 = g_as[node] + adn;
    e0 = (e0 > 0.f) ? e0 : NEG_SLOPE * e0;
    const float exs = __expf(e0);                 // self-loop term

    float4 hv = __ldg(H4 + (long)node * 16 + l);
    float4 acc = make_float4(exs * hv.x, exs * hv.y, exs * hv.z, exs * hv.w);
    float dsum = 0.f;

    const int beg = __ldg(&g_rowptr[node]);
    const int end = __ldg(&g_rowptr[node + 1]);
    for (int k = beg; k < end; k += 16) {
        int idx = k + l;
        int s = 0;
        float ex = 0.f;
        if (idx < end) {
            s = __ldg(&g_adj[idx]);
            float e = __ldg(&g_as[s]) + adn;
            e = (e > 0.f) ? e : NEG_SLOPE * e;
            ex = __expf(e);
        }
        dsum += ex;
        const int cnt = min(16, end - k);
        for (int j = 0; j < cnt; j += 4) {
            int   s0 = __shfl_sync(hm, s, j, 16);
            int   s1 = __shfl_sync(hm, s, j + 1, 16);
            int   s2 = __shfl_sync(hm, s, j + 2, 16);
            int   s3 = __shfl_sync(hm, s, j + 3, 16);
            float x0 = __shfl_sync(hm, ex, j, 16);
            float x1 = __shfl_sync(hm, ex, j + 1, 16);
            float x2 = __shfl_sync(hm, ex, j + 2, 16);
            float x3 = __shfl_sync(hm, ex, j + 3, 16);
            float4 h0 = __ldg(H4 + (long)s0 * 16 + l);
            float4 h1 = __ldg(H4 + (long)s1 * 16 + l);
            float4 h2 = __ldg(H4 + (long)s2 * 16 + l);
            float4 h3 = __ldg(H4 + (long)s3 * 16 + l);
            acc.x += x0 * h0.x; acc.y += x0 * h0.y; acc.z += x0 * h0.z; acc.w += x0 * h0.w;
            acc.x += x1 * h1.x; acc.y += x1 * h1.y; acc.z += x1 * h1.z; acc.w += x1 * h1.w;
            acc.x += x2 * h2.x; acc.y += x2 * h2.y; acc.z += x2 * h2.z; acc.w += x2 * h2.w;
            acc.x += x3 * h3.x; acc.y += x3 * h3.y; acc.z += x3 * h3.z; acc.w += x3 * h3.w;
        }
    }
#pragma unroll
    for (int m = 8; m; m >>= 1) dsum += __shfl_xor_sync(hm, dsum, m, 16);

    const float inv = 1.0f / (dsum + exs);
    float4 bb = __ldg((const float4*)b + l);
    float4 r = make_float4(acc.x * inv + bb.x, acc.y * inv + bb.y,
                           acc.z * inv + bb.z, acc.w * inv + bb.w);

    if (mode == 1) {
        r.x = fmaxf(r.x, 0.f); r.y = fmaxf(r.y, 0.f);
        r.z = fmaxf(r.z, 0.f); r.w = fmaxf(r.w, 0.f);
        ((float4*)g_feat)[(long)node * 16 + l] = r;
    } else {
        // fused global mean pool
        __syncwarp(FULLM);
        r.x += __shfl_xor_sync(FULLM, r.x, 16);
        r.y += __shfl_xor_sync(FULLM, r.y, 16);
        r.z += __shfl_xor_sync(FULLM, r.z, 16);
        r.w += __shfl_xor_sync(FULLM, r.w, 16);
        if (lane < 16) {
            atomicAdd(&sred[4 * l + 0], r.x);
            atomicAdd(&sred[4 * l + 1], r.y);
            atomicAdd(&sred[4 * l + 2], r.z);
            atomicAdd(&sred[4 * l + 3], r.w);
        }
        __syncthreads();
        if (threadIdx.x < 64)
            atomicAdd(&out[threadIdx.x], sred[threadIdx.x] * (1.0f / N_NODES));
    }
}

// ---------------- launch ----------------
extern "C" void kernel_launch(void* const* d_in, const int* in_sizes, int n_in,
                              void* d_out, int out_size) {
    const float* x   = (const float*)d_in[0];
    const int*   ei  = (const int*)d_in[1];
    // d_in[2] = edge_attr (unused; GATConv edge_dim=None)
    const float* W1  = (const float*)d_in[3];
    const float* as1 = (const float*)d_in[4];
    const float* ad1 = (const float*)d_in[5];
    const float* b1  = (const float*)d_in[6];
    const float* W2  = (const float*)d_in[7];
    const float* as2 = (const float*)d_in[8];
    const float* ad2 = (const float*)d_in[9];
    const float* b2  = (const float*)d_in[10];
    float* out = (float*)d_out;

    // (0) layer-1 gemm + dst histogram/rank capture (fused, complementary pipes)
    k_gemm<128, true><<<GB_GEMM + GB_HIST, 256>>>(x, W1, as1, ad1, ei, out);
    // (1) rowptr via single-kernel decoupled lookback scan
    k_scan<<<NB_SCAN, 1024>>>();
    // (2) atomic-free adjacency fill + scratch reset for next call
    k_fill<<<3125, 512>>>(ei);
    // (3) layer-1 aggregation
    k_agg<<<3125, 512>>>(b1, out, 1);
    // (4) layer-2 gemm (+ zero out)
    k_gemm<64, false><<<GB_GEMM, 256>>>(nullptr, W2, as2, ad2, nullptr, out);
    // (5) layer-2 aggregation + fused global mean pool
    k_agg<<<3125, 512>>>(b2, out, 2);
}

// round 11
// speedup vs baseline: 1.3576x; 1.0971x over previous
#include <cuda_runtime.h>

#define N_NODES 100000
#define N_EDGES 1600000
#define NB_SCAN 98              // ceil((N_NODES+1)/1024)
#define NEG_SLOPE 0.2f
#define FULLM 0xffffffffu
#define GB_GEMM 1563            // ceil(N_NODES/64)
#define GB_HIST 6250            // ceil(N_EDGES/256)

// ---------------- scratch (device globals; zero-initialized at module load) ----------
// Cross-call invariant: g_deg and g_tstat are zero at the start of every
// kernel_launch call — module-load zero-init covers the first call; k_fill
// re-zeroes them (after their last use) for every later call. g_m is zeroed
// by k_fill each call before agg2 accumulates into it.
__device__ int      g_deg[N_NODES + 1];
__device__ int      g_rowptr[N_NODES + 1];
__device__ int      g_ord[N_EDGES];       // within-dst-bucket rank of each edge
__device__ unsigned g_tstat[NB_SCAN];     // lookback status: [31:30] flag (1=agg,2=prefix), [29:0] value
__device__ int      g_adj[N_EDGES];       // src indices in CSR (dst-grouped) order
__device__ float    g_h[N_NODES * 64];    // layer-1 transformed features
__device__ float    g_feat[N_NODES * 64]; // layer-1 output (input to layer-2 attention)
__device__ float    g_as[N_NODES];        // layer-1 logit halves
__device__ float    g_ad[N_NODES];
__device__ float    g_as2[N_NODES];       // layer-2 logit halves (feat . u / feat . v)
__device__ float    g_ad2[N_NODES];
__device__ float    g_u[64];              // u = W2^T a_src2
__device__ float    g_v[64];              // v = W2^T a_dst2
__device__ float    g_m[64];              // sum_n (softmax-weighted feat aggregate)

// ---------------- smem-staged SIMT outer-product GEMM + attention logits -------------
// Block = 256 threads -> tile of 64 nodes x 64 outputs. Thread (tx=tid&15,
// ty=tid>>4) owns a 4x4 register tile. X tile and W transposed into k-major
// smem; inner loop per k is 2x LDS.128 + 16 FFMA -> FFMA-pipe bound.
// HIST blocks (>= GB_GEMM) run the dst-degree histogram + bucket-rank capture
// (LSU/atomic-bound, overlaps the FMA-bound gemm blocks for ~free). The
// atomicAdd return value IS the edge's rank within its dst bucket -> k_fill
// needs no atomics.
__global__ void __launch_bounds__(256)
k_gemm1(const float* __restrict__ X,
        const float* __restrict__ W,
        const float* __restrict__ avsrc,
        const float* __restrict__ avdst,
        const int* __restrict__ ei) {
    if (blockIdx.x >= GB_GEMM) {
        int e = (blockIdx.x - GB_GEMM) * 256 + threadIdx.x;
        if (e < N_EDGES) {
            int d = __ldg(&ei[N_EDGES + e]);
            g_ord[e] = atomicAdd(&g_deg[d + 1], 1);
        }
        return;
    }
    __shared__ float xs[64][68];     // xs[k][node]
    __shared__ float ws[64][68];     // ws[k][out]
    __shared__ float sASP[64][17];   // per-node logit partials over ty
    __shared__ float sADP[64][17];

    const int tid = threadIdx.x;
    const int tx  = tid & 15;
    const int ty  = tid >> 4;
    const int nbase = blockIdx.x * 64;
    const int C = 32;                // 128 floats = 32 float4 per row

    const float4* X4 = (const float4*)X;
    const float4* W4 = (const float4*)W;

    float acc[4][4];
#pragma unroll
    for (int i = 0; i < 4; i++)
#pragma unroll
        for (int o = 0; o < 4; o++) acc[i][o] = 0.f;

#pragma unroll
    for (int ch = 0; ch < 2; ch++) {
        const int kc4 = ch * 16;     // float4 column offset of this k-chunk
        __syncthreads();
        // stage X-tile and W chunk, transposing to k-major.
        // idx bits: [1:0]->c4 low, [7:2]->row, [9:8]->c4 high
        // -> warp covers 8 rows x 4 c4: 64B-coalesced global reads, 2-way STS banks.
#pragma unroll
        for (int it = 0; it < 4; it++) {
            int idx = tid + it * 256;
            int c4  = (idx & 3) | (((idx >> 8) & 3) << 2);
            int r   = (idx >> 2) & 63;
            int xrow = min(nbase + r, N_NODES - 1);     // clamp tail (stores guarded)
            float4 v = __ldg(&X4[(long)xrow * C + kc4 + c4]);
            xs[c4 * 4 + 0][r] = v.x; xs[c4 * 4 + 1][r] = v.y;
            xs[c4 * 4 + 2][r] = v.z; xs[c4 * 4 + 3][r] = v.w;
            float4 wv = __ldg(&W4[(long)r * C + kc4 + c4]);
            ws[c4 * 4 + 0][r] = wv.x; ws[c4 * 4 + 1][r] = wv.y;
            ws[c4 * 4 + 2][r] = wv.z; ws[c4 * 4 + 3][r] = wv.w;
        }
        __syncthreads();

#pragma unroll 4
        for (int kk = 0; kk < 64; kk++) {
            float4 xv = *(const float4*)&xs[kk][tx * 4];   // 4 nodes at this k
            float4 wv = *(const float4*)&ws[kk][ty * 4];   // 4 outs at this k
            acc[0][0] += xv.x * wv.x; acc[0][1] += xv.x * wv.y;
            acc[0][2] += xv.x * wv.z; acc[0][3] += xv.x * wv.w;
            acc[1][0] += xv.y * wv.x; acc[1][1] += xv.y * wv.y;
            acc[1][2] += xv.y * wv.z; acc[1][3] += xv.y * wv.w;
            acc[2][0] += xv.z * wv.x; acc[2][1] += xv.z * wv.y;
            acc[2][2] += xv.z * wv.z; acc[2][3] += xv.z * wv.w;
            acc[3][0] += xv.w * wv.x; acc[3][1] += xv.w * wv.y;
            acc[3][2] += xv.w * wv.z; acc[3][3] += xv.w * wv.w;
        }
    }

    // store h
    float4* H4 = (float4*)g_h;
#pragma unroll
    for (int i = 0; i < 4; i++) {
        int node = nbase + tx * 4 + i;
        if (node < N_NODES)
            H4[(long)node * 16 + ty] =
                make_float4(acc[i][0], acc[i][1], acc[i][2], acc[i][3]);
    }

    // attention logit partials: as = h . a_src, ad = h . a_dst (deterministic tree)
    float4 sv = __ldg((const float4*)avsrc + ty);
    float4 dv = __ldg((const float4*)avdst + ty);
#pragma unroll
    for (int i = 0; i < 4; i++) {
        float sp = acc[i][0] * sv.x + acc[i][1] * sv.y + acc[i][2] * sv.z + acc[i][3] * sv.w;
        float dp = acc[i][0] * dv.x + acc[i][1] * dv.y + acc[i][2] * dv.z + acc[i][3] * dv.w;
        sASP[tx * 4 + i][ty] = sp;
        sADP[tx * 4 + i][ty] = dp;
    }
    __syncthreads();
    if (tid < 64) {
        int node = nbase + tid;
        if (node < N_NODES) {
            float s = 0.f, d = 0.f;
#pragma unroll
            for (int j = 0; j < 16; j++) { s += sASP[tid][j]; d += sADP[tid][j]; }
            g_as[node] = s;
            g_ad[node] = d;
        }
    }
}

// ---------------- single-kernel decoupled-lookback scan of g_deg -> g_rowptr ----------
// 98 tiles of 1024; 98 blocks co-resident so polling always makes progress.
// Status word packs flag+value so the single 32-bit atomic publish needs no fence.
__global__ void __launch_bounds__(1024) k_scan() {
    __shared__ int s[1024];
    __shared__ int s_prefix;
    const int t = threadIdx.x;
    const int tile = blockIdx.x;
    const int i = tile * 1024 + t;
    int v = (i <= N_NODES) ? g_deg[i] : 0;
    s[t] = v;
    __syncthreads();
    for (int off = 1; off < 1024; off <<= 1) {
        int x = (t >= off) ? s[t - off] : 0;
        __syncthreads();
        s[t] += x;
        __syncthreads();
    }
    const int inc = s[t];
    const int total = s[1023];

    if (t == 0) {
        if (tile == 0) {
            atomicExch(&g_tstat[0], (2u << 30) | (unsigned)total);
            s_prefix = 0;
        } else {
            atomicExch(&g_tstat[tile], (1u << 30) | (unsigned)total);
            int prefix = 0;
            int p = tile - 1;
            while (true) {
                unsigned st = *(volatile unsigned*)&g_tstat[p];
                unsigned f = st >> 30;
                if (f == 0u) continue;
                prefix += (int)(st & 0x3FFFFFFFu);
                if (f == 2u) break;
                p--;
            }
            atomicExch(&g_tstat[tile], (2u << 30) | (unsigned)(prefix + total));
            s_prefix = prefix;
        }
    }
    __syncthreads();
    const int val = inc + s_prefix;
    if (i <= N_NODES) g_rowptr[i] = val;
}

// ---------------- atomic-free adjacency fill + u/v precompute + cleanup -------------
// pos = rowptr[dst] + precomputed bucket rank: loads + one scattered store only.
// Block 3125 computes u = W2^T a_src2, v = W2^T a_dst2 (layer-2 logit vectors)
// and zeroes g_m for this call's agg2.
__global__ void __launch_bounds__(512) k_fill(const int* __restrict__ ei,
                                              const float* __restrict__ W2,
                                              const float* __restrict__ as2v,
                                              const float* __restrict__ ad2v) {
    if (blockIdx.x == 3125) {
        int k = threadIdx.x;
        if (k < 64) {
            float u = 0.f, v = 0.f;
#pragma unroll 8
            for (int o = 0; o < 64; o++) {
                float w = __ldg(&W2[o * 64 + k]);
                u += __ldg(&as2v[o]) * w;
                v += __ldg(&ad2v[o]) * w;
            }
            g_u[k] = u;
            g_v[k] = v;
            g_m[k] = 0.f;
        }
        return;
    }
    int gid = blockIdx.x * 512 + threadIdx.x;
    if (gid <= N_NODES) g_deg[gid] = 0;       // reset for next kernel_launch call
    if (gid < NB_SCAN) g_tstat[gid] = 0u;     // reset lookback status
    if (gid < N_EDGES) {
        int d   = __ldg(&ei[N_EDGES + gid]);
        int pos = __ldg(&g_rowptr[d]) + g_ord[gid];
        g_adj[pos] = __ldg(&ei[gid]);
    }
}

// ---------------- half-warp-per-node softmax aggregation (atomic-free) ---------------
// 16 lanes own one node; lane l holds features [4l, 4l+4). One LDG.128 across
// the 16 lanes fetches a full 256B feature row per edge. Single predicated
// 4-wide batch loop: invalid tail slots carry (s=0, ex=0) -> gather h[0] with
// zero weight, keeping MLP 4 on tail edges. exp-max subtraction omitted:
// logits are O(10) so fp32 exp cannot overflow and the ratio is unchanged.
// mode 1 (layer 1): gathers g_h with logits (g_as,g_ad); epilogue applies
//   bias+relu, stores g_feat, AND computes the layer-2 logit halves
//   as2 = feat.u, ad2 = feat.v in-register (replaces the whole layer-2 gemm:
//   out = W2 (mean_n sum_e alpha feat[src]) + b2 by linearity).
// mode 2 (layer 2): gathers g_feat with logits (g_as2,g_ad2); pools the
//   normalized per-node aggregate into g_m (k_fin applies W2, 1/N, b2).
__global__ void __launch_bounds__(512)
k_agg(const float* __restrict__ b, int mode) {
    __shared__ float sred[64];
    if (mode == 2) {
        if (threadIdx.x < 64) sred[threadIdx.x] = 0.f;
        __syncthreads();
    }
    const int lane = threadIdx.x & 31;
    const int l = lane & 15;
    const unsigned hm = 0xFFFFu << (lane & 16);
    const int node = (blockIdx.x * 512 + threadIdx.x) >> 4;   // exact: 3125*512/16 = 100000

    const float4* H4 = (mode == 1) ? (const float4*)g_h : (const float4*)g_feat;
    const float* asp = (mode == 1) ? g_as : g_as2;
    const float* adp = (mode == 1) ? g_ad : g_ad2;

    const float adn = adp[node];
    float e0 = asp[node] + adn;
    e0 = (e0 > 0.f) ? e0 : NEG_SLOPE * e0;
    const float exs = __expf(e0);                 // self-loop term

    float4 hv = __ldg(H4 + (long)node * 16 + l);
    float4 acc = make_float4(exs * hv.x, exs * hv.y, exs * hv.z, exs * hv.w);
    float dsum = 0.f;

    const int beg = __ldg(&g_rowptr[node]);
    const int end = __ldg(&g_rowptr[node + 1]);
    for (int k = beg; k < end; k += 16) {
        int idx = k + l;
        int s = 0;
        float ex = 0.f;
        if (idx < end) {
            s = __ldg(&g_adj[idx]);
            float e = __ldg(&asp[s]) + adn;
            e = (e > 0.f) ? e : NEG_SLOPE * e;
            ex = __expf(e);
        }
        dsum += ex;
        const int cnt = min(16, end - k);
        for (int j = 0; j < cnt; j += 4) {
            int   s0 = __shfl_sync(hm, s, j, 16);
            int   s1 = __shfl_sync(hm, s, j + 1, 16);
            int   s2 = __shfl_sync(hm, s, j + 2, 16);
            int   s3 = __shfl_sync(hm, s, j + 3, 16);
            float x0 = __shfl_sync(hm, ex, j, 16);
            float x1 = __shfl_sync(hm, ex, j + 1, 16);
            float x2 = __shfl_sync(hm, ex, j + 2, 16);
            float x3 = __shfl_sync(hm, ex, j + 3, 16);
            float4 h0 = __ldg(H4 + (long)s0 * 16 + l);
            float4 h1 = __ldg(H4 + (long)s1 * 16 + l);
            float4 h2 = __ldg(H4 + (long)s2 * 16 + l);
            float4 h3 = __ldg(H4 + (long)s3 * 16 + l);
            acc.x += x0 * h0.x; acc.y += x0 * h0.y; acc.z += x0 * h0.z; acc.w += x0 * h0.w;
            acc.x += x1 * h1.x; acc.y += x1 * h1.y; acc.z += x1 * h1.z; acc.w += x1 * h1.w;
            acc.x += x2 * h2.x; acc.y += x2 * h2.y; acc.z += x2 * h2.z; acc.w += x2 * h2.w;
            acc.x += x3 * h3.x; acc.y += x3 * h3.y; acc.z += x3 * h3.z; acc.w += x3 * h3.w;
        }
    }
#pragma unroll
    for (int m = 8; m; m >>= 1) dsum += __shfl_xor_sync(hm, dsum, m, 16);

    const float inv = 1.0f / (dsum + exs);

    if (mode == 1) {
        float4 bb = __ldg((const float4*)b + l);
        float4 r = make_float4(fmaxf(acc.x * inv + bb.x, 0.f),
                               fmaxf(acc.y * inv + bb.y, 0.f),
                               fmaxf(acc.z * inv + bb.z, 0.f),
                               fmaxf(acc.w * inv + bb.w, 0.f));
        ((float4*)g_feat)[(long)node * 16 + l] = r;
        // layer-2 logit halves from the in-register feat row
        float4 uu = __ldg((const float4*)g_u + l);
        float4 vv = __ldg((const float4*)g_v + l);
        float sp = r.x * uu.x + r.y * uu.y + r.z * uu.z + r.w * uu.w;
        float dp = r.x * vv.x + r.y * vv.y + r.z * vv.z + r.w * vv.w;
#pragma unroll
        for (int m = 8; m; m >>= 1) {
            sp += __shfl_xor_sync(hm, sp, m, 16);
            dp += __shfl_xor_sync(hm, dp, m, 16);
        }
        if (l == 0) { g_as2[node] = sp; g_ad2[node] = dp; }
    } else {
        // pool normalized aggregate (no bias; W2/b2/(1/N) applied in k_fin)
        float4 r = make_float4(acc.x * inv, acc.y * inv, acc.z * inv, acc.w * inv);
        __syncwarp(FULLM);
        r.x += __shfl_xor_sync(FULLM, r.x, 16);
        r.y += __shfl_xor_sync(FULLM, r.y, 16);
        r.z += __shfl_xor_sync(FULLM, r.z, 16);
        r.w += __shfl_xor_sync(FULLM, r.w, 16);
        if (lane < 16) {
            atomicAdd(&sred[4 * l + 0], r.x);
            atomicAdd(&sred[4 * l + 1], r.y);
            atomicAdd(&sred[4 * l + 2], r.z);
            atomicAdd(&sred[4 * l + 3], r.w);
        }
        __syncthreads();
        if (threadIdx.x < 64)
            atomicAdd(&g_m[threadIdx.x], sred[threadIdx.x]);
    }
}

// ---------------- final projection: out = W2 (g_m / N) + b2 ----------------
__global__ void k_fin(const float* __restrict__ W2,
                      const float* __restrict__ b2,
                      float* __restrict__ out) {
    int o = threadIdx.x;
    float s = 0.f;
#pragma unroll 8
    for (int k = 0; k < 64; k++)
        s += __ldg(&W2[o * 64 + k]) * g_m[k];
    out[o] = s * (1.0f / N_NODES) + __ldg(&b2[o]);
}

// ---------------- launch ----------------
extern "C" void kernel_launch(void* const* d_in, const int* in_sizes, int n_in,
                              void* d_out, int out_size) {
    const float* x   = (const float*)d_in[0];
    const int*   ei  = (const int*)d_in[1];
    // d_in[2] = edge_attr (unused; GATConv edge_dim=None)
    const float* W1  = (const float*)d_in[3];
    const float* as1 = (const float*)d_in[4];
    const float* ad1 = (const float*)d_in[5];
    const float* b1  = (const float*)d_in[6];
    const float* W2  = (const float*)d_in[7];
    const float* as2 = (const float*)d_in[8];
    const float* ad2 = (const float*)d_in[9];
    const float* b2  = (const float*)d_in[10];
    float* out = (float*)d_out;

    // (0) layer-1 gemm + dst histogram/rank capture (fused, complementary pipes)
    k_gemm1<<<GB_GEMM + GB_HIST, 256>>>(x, W1, as1, ad1, ei);
    // (1) rowptr via single-kernel decoupled lookback scan
    k_scan<<<NB_SCAN, 1024>>>();
    // (2) atomic-free adjacency fill + u/v vectors + scratch reset
    k_fill<<<3126, 512>>>(ei, W2, as2, ad2);
    // (3) layer-1 aggregation (also emits layer-2 logit halves)
    k_agg<<<3125, 512>>>(b1, 1);
    // (4) layer-2 aggregation -> pooled mean vector g_m
    k_agg<<<3125, 512>>>(nullptr, 2);
    // (5) out = W2 (g_m/N) + b2
    k_fin<<<1, 64>>>(W2, b2, out);
}

// round 12
// speedup vs baseline: 1.4251x; 1.0497x over previous
#include <cuda_runtime.h>
#include <cuda_fp16.h>

#define N_NODES 100000
#define N_EDGES 1600000
#define NB_SCAN 98              // ceil((N_NODES+1)/1024)
#define NEG_SLOPE 0.2f
#define FULLM 0xffffffffu
#define GB_GEMM 1563            // ceil(N_NODES/64)
#define GB_HIST 6250            // ceil(N_EDGES/256)

// ---------------- scratch (device globals; zero-initialized at module load) ----------
// Cross-call invariant: g_deg and g_tstat are zero at the start of every
// kernel_launch call — module-load zero-init covers the first call; k_fill
// re-zeroes them (after their last use) for every later call. g_m is zeroed
// by k_fill each call before agg2 accumulates into it.
__device__ int      g_deg[N_NODES + 1];
__device__ int      g_rowptr[N_NODES + 1];
__device__ int      g_ord[N_EDGES];       // within-dst-bucket rank of each edge
__device__ unsigned g_tstat[NB_SCAN];     // lookback status: [31:30] flag (1=agg,2=prefix), [29:0] value
__device__ int      g_adj[N_EDGES];       // src indices in CSR (dst-grouped) order
__device__ uint2    g_h[N_NODES * 16];    // layer-1 features, fp16 rows (64 x half = 128B/row)
__device__ uint2    g_feat[N_NODES * 16]; // layer-1 output, fp16 rows (layer-2 gather source)
__device__ float    g_as[N_NODES];        // layer-1 logit halves (fp32)
__device__ float    g_ad[N_NODES];
__device__ float    g_as2[N_NODES];       // layer-2 logit halves (feat . u / feat . v)
__device__ float    g_ad2[N_NODES];
__device__ float    g_u[64];              // u = W2^T a_src2
__device__ float    g_v[64];              // v = W2^T a_dst2
__device__ float    g_m[64];              // softmax-weighted feat aggregate (sum over nodes)

__device__ __forceinline__ uint2 pack4h(float a, float b, float c, float d) {
    __half2 p0 = __floats2half2_rn(a, b);
    __half2 p1 = __floats2half2_rn(c, d);
    uint2 r;
    r.x = *reinterpret_cast<unsigned*>(&p0);
    r.y = *reinterpret_cast<unsigned*>(&p1);
    return r;
}
__device__ __forceinline__ float4 unpack4h(uint2 v) {
    float2 f0 = __half22float2(*reinterpret_cast<__half2*>(&v.x));
    float2 f1 = __half22float2(*reinterpret_cast<__half2*>(&v.y));
    return make_float4(f0.x, f0.y, f1.x, f1.y);
}

// ---------------- smem-staged SIMT outer-product GEMM + attention logits -------------
// Block = 256 threads -> tile of 64 nodes x 64 outputs. Thread (tx=tid&15,
// ty=tid>>4) owns a 4x4 register tile. X tile and W transposed into k-major
// smem; inner loop per k is 2x LDS.128 + 16 FFMA -> FFMA-pipe bound.
// h is stored as fp16 rows (accumulation and logits stay fp32).
// HIST blocks (>= GB_GEMM) run the dst-degree histogram + bucket-rank capture;
// the atomicAdd return value IS the edge's rank -> k_fill needs no atomics.
__global__ void __launch_bounds__(256)
k_gemm1(const float* __restrict__ X,
        const float* __restrict__ W,
        const float* __restrict__ avsrc,
        const float* __restrict__ avdst,
        const int* __restrict__ ei) {
    if (blockIdx.x >= GB_GEMM) {
        int e = (blockIdx.x - GB_GEMM) * 256 + threadIdx.x;
        if (e < N_EDGES) {
            int d = __ldg(&ei[N_EDGES + e]);
            g_ord[e] = atomicAdd(&g_deg[d + 1], 1);
        }
        return;
    }
    __shared__ float xs[64][68];     // xs[k][node]
    __shared__ float ws[64][68];     // ws[k][out]
    __shared__ float sASP[64][17];   // per-node logit partials over ty
    __shared__ float sADP[64][17];

    const int tid = threadIdx.x;
    const int tx  = tid & 15;
    const int ty  = tid >> 4;
    const int nbase = blockIdx.x * 64;
    const int C = 32;                // 128 floats = 32 float4 per row

    const float4* X4 = (const float4*)X;
    const float4* W4 = (const float4*)W;

    float acc[4][4];
#pragma unroll
    for (int i = 0; i < 4; i++)
#pragma unroll
        for (int o = 0; o < 4; o++) acc[i][o] = 0.f;

#pragma unroll
    for (int ch = 0; ch < 2; ch++) {
        const int kc4 = ch * 16;     // float4 column offset of this k-chunk
        __syncthreads();
        // stage X-tile and W chunk, transposing to k-major.
        // idx bits: [1:0]->c4 low, [7:2]->row, [9:8]->c4 high
        // -> warp covers 8 rows x 4 c4: 64B-coalesced global reads, 2-way STS banks.
#pragma unroll
        for (int it = 0; it < 4; it++) {
            int idx = tid + it * 256;
            int c4  = (idx & 3) | (((idx >> 8) & 3) << 2);
            int r   = (idx >> 2) & 63;
            int xrow = min(nbase + r, N_NODES - 1);     // clamp tail (stores guarded)
            float4 v = __ldg(&X4[(long)xrow * C + kc4 + c4]);
            xs[c4 * 4 + 0][r] = v.x; xs[c4 * 4 + 1][r] = v.y;
            xs[c4 * 4 + 2][r] = v.z; xs[c4 * 4 + 3][r] = v.w;
            float4 wv = __ldg(&W4[(long)r * C + kc4 + c4]);
            ws[c4 * 4 + 0][r] = wv.x; ws[c4 * 4 + 1][r] = wv.y;
            ws[c4 * 4 + 2][r] = wv.z; ws[c4 * 4 + 3][r] = wv.w;
        }
        __syncthreads();

#pragma unroll 4
        for (int kk = 0; kk < 64; kk++) {
            float4 xv = *(const float4*)&xs[kk][tx * 4];   // 4 nodes at this k
            float4 wv = *(const float4*)&ws[kk][ty * 4];   // 4 outs at this k
            acc[0][0] += xv.x * wv.x; acc[0][1] += xv.x * wv.y;
            acc[0][2] += xv.x * wv.z; acc[0][3] += xv.x * wv.w;
            acc[1][0] += xv.y * wv.x; acc[1][1] += xv.y * wv.y;
            acc[1][2] += xv.y * wv.z; acc[1][3] += xv.y * wv.w;
            acc[2][0] += xv.z * wv.x; acc[2][1] += xv.z * wv.y;
            acc[2][2] += xv.z * wv.z; acc[2][3] += xv.z * wv.w;
            acc[3][0] += xv.w * wv.x; acc[3][1] += xv.w * wv.y;
            acc[3][2] += xv.w * wv.z; acc[3][3] += xv.w * wv.w;
        }
    }

    // store h (fp16 rows)
#pragma unroll
    for (int i = 0; i < 4; i++) {
        int node = nbase + tx * 4 + i;
        if (node < N_NODES)
            g_h[(long)node * 16 + ty] = pack4h(acc[i][0], acc[i][1], acc[i][2], acc[i][3]);
    }

    // attention logit partials: as = h . a_src, ad = h . a_dst (fp32, deterministic tree)
    float4 sv = __ldg((const float4*)avsrc + ty);
    float4 dv = __ldg((const float4*)avdst + ty);
#pragma unroll
    for (int i = 0; i < 4; i++) {
        float sp = acc[i][0] * sv.x + acc[i][1] * sv.y + acc[i][2] * sv.z + acc[i][3] * sv.w;
        float dp = acc[i][0] * dv.x + acc[i][1] * dv.y + acc[i][2] * dv.z + acc[i][3] * dv.w;
        sASP[tx * 4 + i][ty] = sp;
        sADP[tx * 4 + i][ty] = dp;
    }
    __syncthreads();
    if (tid < 64) {
        int node = nbase + tid;
        if (node < N_NODES) {
            float s = 0.f, d = 0.f;
#pragma unroll
            for (int j = 0; j < 16; j++) { s += sASP[tid][j]; d += sADP[tid][j]; }
            g_as[node] = s;
            g_ad[node] = d;
        }
    }
}

// ---------------- single-kernel decoupled-lookback scan of g_deg -> g_rowptr ----------
__global__ void __launch_bounds__(1024) k_scan() {
    __shared__ int s[1024];
    __shared__ int s_prefix;
    const int t = threadIdx.x;
    const int tile = blockIdx.x;
    const int i = tile * 1024 + t;
    int v = (i <= N_NODES) ? g_deg[i] : 0;
    s[t] = v;
    __syncthreads();
    for (int off = 1; off < 1024; off <<= 1) {
        int x = (t >= off) ? s[t - off] : 0;
        __syncthreads();
        s[t] += x;
        __syncthreads();
    }
    const int inc = s[t];
    const int total = s[1023];

    if (t == 0) {
        if (tile == 0) {
            atomicExch(&g_tstat[0], (2u << 30) | (unsigned)total);
            s_prefix = 0;
        } else {
            atomicExch(&g_tstat[tile], (1u << 30) | (unsigned)total);
            int prefix = 0;
            int p = tile - 1;
            while (true) {
                unsigned st = *(volatile unsigned*)&g_tstat[p];
                unsigned f = st >> 30;
                if (f == 0u) continue;
                prefix += (int)(st & 0x3FFFFFFFu);
                if (f == 2u) break;
                p--;
            }
            atomicExch(&g_tstat[tile], (2u << 30) | (unsigned)(prefix + total));
            s_prefix = prefix;
        }
    }
    __syncthreads();
    const int val = inc + s_prefix;
    if (i <= N_NODES) g_rowptr[i] = val;
}

// ---------------- atomic-free adjacency fill + u/v precompute + cleanup -------------
// pos = rowptr[dst] + precomputed bucket rank: loads + one scattered store only.
// Block 3125 computes u = W2^T a_src2, v = W2^T a_dst2 and zeroes g_m.
__global__ void __launch_bounds__(512) k_fill(const int* __restrict__ ei,
                                              const float* __restrict__ W2,
                                              const float* __restrict__ as2v,
                                              const float* __restrict__ ad2v) {
    if (blockIdx.x == 3125) {
        int k = threadIdx.x;
        if (k < 64) {
            float u = 0.f, v = 0.f;
#pragma unroll 8
            for (int o = 0; o < 64; o++) {
                float w = __ldg(&W2[o * 64 + k]);
                u += __ldg(&as2v[o]) * w;
                v += __ldg(&ad2v[o]) * w;
            }
            g_u[k] = u;
            g_v[k] = v;
            g_m[k] = 0.f;
        }
        return;
    }
    int gid = blockIdx.x * 512 + threadIdx.x;
    if (gid <= N_NODES) g_deg[gid] = 0;       // reset for next kernel_launch call
    if (gid < NB_SCAN) g_tstat[gid] = 0u;     // reset lookback status
    if (gid < N_EDGES) {
        int d   = __ldg(&ei[N_EDGES + gid]);
        int pos = __ldg(&g_rowptr[d]) + g_ord[gid];
        g_adj[pos] = __ldg(&ei[gid]);
    }
}

// ---------------- half-warp-per-node softmax aggregation (atomic-free) ---------------
// 16 lanes own one node; lane l holds features [4l, 4l+4) as fp16 (8B/lane):
// one LDG.64 across 16 lanes = one 128B wavefront per edge row (was two).
// Accumulation, logits, softmax all fp32. Single predicated 4-wide batch loop:
// invalid tail slots carry (s=0, ex=0) so they gather row 0 with zero weight.
// exp-max subtraction omitted: logits are O(10), fp32 exp cannot overflow.
// mode 1: bias+relu, store g_feat (fp16) + emit layer-2 logit halves
//         as2 = feat.u, ad2 = feat.v (replaces the layer-2 gemm by linearity).
// mode 2: pool normalized aggregate into g_m (k_fin applies W2, 1/N, b2).
__global__ void __launch_bounds__(512)
k_agg(const float* __restrict__ b, int mode) {
    __shared__ float sred[64];
    if (mode == 2) {
        if (threadIdx.x < 64) sred[threadIdx.x] = 0.f;
        __syncthreads();
    }
    const int lane = threadIdx.x & 31;
    const int l = lane & 15;
    const unsigned hm = 0xFFFFu << (lane & 16);
    const int node = (blockIdx.x * 512 + threadIdx.x) >> 4;   // exact: 3125*512/16 = 100000

    const uint2* H = (mode == 1) ? g_h : g_feat;
    const float* asp = (mode == 1) ? g_as : g_as2;
    const float* adp = (mode == 1) ? g_ad : g_ad2;

    const float adn = adp[node];
    float e0 = asp[node] + adn;
    e0 = (e0 > 0.f) ? e0 : NEG_SLOPE * e0;
    const float exs = __expf(e0);                 // self-loop term

    float4 hv = unpack4h(__ldg(H + (long)node * 16 + l));
    float4 acc = make_float4(exs * hv.x, exs * hv.y, exs * hv.z, exs * hv.w);
    float dsum = 0.f;

    const int beg = __ldg(&g_rowptr[node]);
    const int end = __ldg(&g_rowptr[node + 1]);
    for (int k = beg; k < end; k += 16) {
        int idx = k + l;
        int s = 0;
        float ex = 0.f;
        if (idx < end) {
            s = __ldg(&g_adj[idx]);
            float e = __ldg(&asp[s]) + adn;
            e = (e > 0.f) ? e : NEG_SLOPE * e;
            ex = __expf(e);
        }
        dsum += ex;
        const int cnt = min(16, end - k);
        for (int j = 0; j < cnt; j += 4) {
            int   s0 = __shfl_sync(hm, s, j, 16);
            int   s1 = __shfl_sync(hm, s, j + 1, 16);
            int   s2 = __shfl_sync(hm, s, j + 2, 16);
            int   s3 = __shfl_sync(hm, s, j + 3, 16);
            float x0 = __shfl_sync(hm, ex, j, 16);
            float x1 = __shfl_sync(hm, ex, j + 1, 16);
            float x2 = __shfl_sync(hm, ex, j + 2, 16);
            float x3 = __shfl_sync(hm, ex, j + 3, 16);
            float4 h0 = unpack4h(__ldg(H + (long)s0 * 16 + l));
            float4 h1 = unpack4h(__ldg(H + (long)s1 * 16 + l));
            float4 h2 = unpack4h(__ldg(H + (long)s2 * 16 + l));
            float4 h3 = unpack4h(__ldg(H + (long)s3 * 16 + l));
            acc.x += x0 * h0.x; acc.y += x0 * h0.y; acc.z += x0 * h0.z; acc.w += x0 * h0.w;
            acc.x += x1 * h1.x; acc.y += x1 * h1.y; acc.z += x1 * h1.z; acc.w += x1 * h1.w;
            acc.x += x2 * h2.x; acc.y += x2 * h2.y; acc.z += x2 * h2.z; acc.w += x2 * h2.w;
            acc.x += x3 * h3.x; acc.y += x3 * h3.y; acc.z += x3 * h3.z; acc.w += x3 * h3.w;
        }
    }
#pragma unroll
    for (int m = 8; m; m >>= 1) dsum += __shfl_xor_sync(hm, dsum, m, 16);

    const float inv = 1.0f / (dsum + exs);

    if (mode == 1) {
        float4 bb = __ldg((const float4*)b + l);
        float4 r = make_float4(fmaxf(acc.x * inv + bb.x, 0.f),
                               fmaxf(acc.y * inv + bb.y, 0.f),
                               fmaxf(acc.z * inv + bb.z, 0.f),
                               fmaxf(acc.w * inv + bb.w, 0.f));
        g_feat[(long)node * 16 + l] = pack4h(r.x, r.y, r.z, r.w);
        // layer-2 logit halves from the in-register (fp32) feat row
        float4 uu = __ldg((const float4*)g_u + l);
        float4 vv = __ldg((const float4*)g_v + l);
        float sp = r.x * uu.x + r.y * uu.y + r.z * uu.z + r.w * uu.w;
        float dp = r.x * vv.x + r.y * vv.y + r.z * vv.z + r.w * vv.w;
#pragma unroll
        for (int m = 8; m; m >>= 1) {
            sp += __shfl_xor_sync(hm, sp, m, 16);
            dp += __shfl_xor_sync(hm, dp, m, 16);
        }
        if (l == 0) { g_as2[node] = sp; g_ad2[node] = dp; }
    } else {
        // pool normalized aggregate (W2/b2/(1/N) applied in k_fin)
        float4 r = make_float4(acc.x * inv, acc.y * inv, acc.z * inv, acc.w * inv);
        __syncwarp(FULLM);
        r.x += __shfl_xor_sync(FULLM, r.x, 16);
        r.y += __shfl_xor_sync(FULLM, r.y, 16);
        r.z += __shfl_xor_sync(FULLM, r.z, 16);
        r.w += __shfl_xor_sync(FULLM, r.w, 16);
        if (lane < 16) {
            atomicAdd(&sred[4 * l + 0], r.x);
            atomicAdd(&sred[4 * l + 1], r.y);
            atomicAdd(&sred[4 * l + 2], r.z);
            atomicAdd(&sred[4 * l + 3], r.w);
        }
        __syncthreads();
        if (threadIdx.x < 64)
            atomicAdd(&g_m[threadIdx.x], sred[threadIdx.x]);
    }
}

// ---------------- final projection: out = W2 (g_m / N) + b2 ----------------
__global__ void k_fin(const float* __restrict__ W2,
                      const float* __restrict__ b2,
                      float* __restrict__ out) {
    int o = threadIdx.x;
    float s = 0.f;
#pragma unroll 8
    for (int k = 0; k < 64; k++)
        s += __ldg(&W2[o * 64 + k]) * g_m[k];
    out[o] = s * (1.0f / N_NODES) + __ldg(&b2[o]);
}

// ---------------- launch ----------------
extern "C" void kernel_launch(void* const* d_in, const int* in_sizes, int n_in,
                              void* d_out, int out_size) {
    const float* x   = (const float*)d_in[0];
    const int*   ei  = (const int*)d_in[1];
    // d_in[2] = edge_attr (unused; GATConv edge_dim=None)
    const float* W1  = (const float*)d_in[3];
    const float* as1 = (const float*)d_in[4];
    const float* ad1 = (const float*)d_in[5];
    const float* b1  = (const float*)d_in[6];
    const float* W2  = (const float*)d_in[7];
    const float* as2 = (const float*)d_in[8];
    const float* ad2 = (const float*)d_in[9];
    const float* b2  = (const float*)d_in[10];
    float* out = (float*)d_out;

    // (0) layer-1 gemm + dst histogram/rank capture (fused, complementary pipes)
    k_gemm1<<<GB_GEMM + GB_HIST, 256>>>(x, W1, as1, ad1, ei);
    // (1) rowptr via single-kernel decoupled lookback scan
    k_scan<<<NB_SCAN, 1024>>>();
    // (2) atomic-free adjacency fill + u/v vectors + scratch reset
    k_fill<<<3126, 512>>>(ei, W2, as2, ad2);
    // (3) layer-1 aggregation (also emits layer-2 logit halves)
    k_agg<<<3125, 512>>>(b1, 1);
    // (4) layer-2 aggregation -> pooled mean vector g_m
    k_agg<<<3125, 512>>>(nullptr, 2);
    // (5) out = W2 (g_m/N) + b2
    k_fin<<<1, 64>>>(W2, b2, out);
}

// round 13
// speedup vs baseline: 1.7171x; 1.2048x over previous
#include <cuda_runtime.h>
#include <cuda_fp16.h>

#define N_NODES 100000
#define N_EDGES 1600000
#define NB_SCAN 98              // ceil((N_NODES+1)/1024)
#define NEG_SLOPE 0.2f
#define FULLM 0xffffffffu
#define GB_G1 782               // ceil(N_NODES/128) gemm tiles
#define GB_HIST 6250            // ceil(N_EDGES/256)

// ---------------- scratch (device globals; zero-initialized at module load) ----------
// Cross-call invariant: g_deg and g_tstat are zero at the start of every
// kernel_launch call — module-load zero-init covers the first call; k_fill
// re-zeroes them (after their last use) for every later call. g_m is zeroed
// by k_fill each call before agg2 accumulates into it.
__device__ int      g_deg[N_NODES + 1];
__device__ int      g_rowptr[N_NODES + 1];
__device__ int      g_ord[N_EDGES];       // within-dst-bucket rank of each edge
__device__ unsigned g_tstat[NB_SCAN];     // lookback status: [31:30] flag (1=agg,2=prefix), [29:0] value
__device__ int      g_adj[N_EDGES];       // src indices in CSR (dst-grouped) order
__device__ uint2    g_h[N_NODES * 16];    // layer-1 features, fp16 rows (64 x half = 128B/row)
__device__ uint2    g_feat[N_NODES * 16]; // layer-1 output, fp16 rows (layer-2 gather source)
__device__ float    g_as[N_NODES];        // layer-1 logit halves (fp32)
__device__ float    g_ad[N_NODES];
__device__ float    g_as2[N_NODES];       // layer-2 logit halves (feat . u / feat . v)
__device__ float    g_ad2[N_NODES];
__device__ float    g_u[64];              // u = W2^T a_src2
__device__ float    g_v[64];              // v = W2^T a_dst2
__device__ float    g_m[64];              // softmax-weighted feat aggregate (sum over nodes)

__device__ __forceinline__ uint2 pack4h(float a, float b, float c, float d) {
    __half2 p0 = __floats2half2_rn(a, b);
    __half2 p1 = __floats2half2_rn(c, d);
    uint2 r;
    r.x = *reinterpret_cast<unsigned*>(&p0);
    r.y = *reinterpret_cast<unsigned*>(&p1);
    return r;
}
__device__ __forceinline__ float4 unpack4h(uint2 v) {
    float2 f0 = __half22float2(*reinterpret_cast<__half2*>(&v.x));
    float2 f1 = __half22float2(*reinterpret_cast<__half2*>(&v.y));
    return make_float4(f0.x, f0.y, f1.x, f1.y);
}
__device__ __forceinline__ unsigned tf32b(float f) {
    unsigned r;
    asm("cvt.rna.tf32.f32 %0, %1;" : "=r"(r) : "f"(f));
    return r;
}
__device__ __forceinline__ unsigned packh2(float a, float b) {
    __half2 p = __floats2half2_rn(a, b);
    return *reinterpret_cast<unsigned*>(&p);
}

// ---------------- tf32 mma.sync GEMM (h = X @ W1^T) + attention logits ---------------
// Block = 256 threads = 8 warps; tile 128 nodes x 64 outs. Warp w owns rows
// w*16..+15; per warp 8 n-blocks of m16n8k8 tf32 mma (fp32 accumulate).
// K staged 16 at a time into smem (tf32-converted), row stride 20 words:
// all A/B fragment LDS patterns are bank-conflict-free ((20r+tg) mod 32 is a
// permutation over the warp). Logits reduced in-warp over the 4 quad threads.
// h written as fp16 rows (agg layout). HIST blocks (>= GB_G1) run the
// dst-degree histogram + bucket-rank capture; the atomicAdd return value IS
// the edge's rank -> k_fill needs no atomics.
__global__ void __launch_bounds__(256)
k_gemm1(const float* __restrict__ X,
        const float* __restrict__ W,
        const float* __restrict__ avsrc,
        const float* __restrict__ avdst,
        const int* __restrict__ ei) {
    if (blockIdx.x >= GB_G1) {
        int e = (blockIdx.x - GB_G1) * 256 + threadIdx.x;
        if (e < N_EDGES) {
            int d = __ldg(&ei[N_EDGES + e]);
            g_ord[e] = atomicAdd(&g_deg[d + 1], 1);
        }
        return;
    }
    __shared__ unsigned xs[128][20];   // X chunk, tf32 bits, [row][k0..15], stride 20
    __shared__ unsigned ws[64][20];    // W chunk, tf32 bits, [out][k0..15]

    const int tid  = threadIdx.x;
    const int lane = tid & 31;
    const int wid  = tid >> 5;         // warp 0..7
    const int g    = lane >> 2;        // groupID (row-in-16 / col-in-8)
    const int tg   = lane & 3;         // threadID_in_group
    const int nbase = blockIdx.x * 128;
    const int m0 = wid * 16;

    const float4* X4 = (const float4*)X;   // 32 float4 per 128-float row
    const float4* W4 = (const float4*)W;

    float acc[8][4];
#pragma unroll
    for (int nb = 0; nb < 8; nb++)
#pragma unroll
        for (int i = 0; i < 4; i++) acc[nb][i] = 0.f;

#pragma unroll 1
    for (int ch = 0; ch < 8; ch++) {
        __syncthreads();
        // stage X chunk: 128 rows x 16 k (512 float4, 2 per thread)
#pragma unroll
        for (int it = 0; it < 2; it++) {
            int idx = tid + it * 256;
            int r  = idx >> 2;
            int c4 = idx & 3;
            int xrow = min(nbase + r, N_NODES - 1);        // clamp tail (stores guarded)
            float4 v = __ldg(&X4[(long)xrow * 32 + ch * 4 + c4]);
            *(uint4*)&xs[r][c4 * 4] =
                make_uint4(tf32b(v.x), tf32b(v.y), tf32b(v.z), tf32b(v.w));
        }
        // stage W chunk: 64 rows x 16 k (256 float4, 1 per thread)
        {
            int r  = tid >> 2;
            int c4 = tid & 3;
            float4 v = __ldg(&W4[(long)r * 32 + ch * 4 + c4]);
            *(uint4*)&ws[r][c4 * 4] =
                make_uint4(tf32b(v.x), tf32b(v.y), tf32b(v.z), tf32b(v.w));
        }
        __syncthreads();

#pragma unroll
        for (int ks = 0; ks < 2; ks++) {
            const int kb = ks * 8;
            unsigned a0 = xs[m0 + g][kb + tg];
            unsigned a1 = xs[m0 + g + 8][kb + tg];
            unsigned a2 = xs[m0 + g][kb + tg + 4];
            unsigned a3 = xs[m0 + g + 8][kb + tg + 4];
#pragma unroll
            for (int nb = 0; nb < 8; nb++) {
                unsigned b0 = ws[nb * 8 + g][kb + tg];
                unsigned b1 = ws[nb * 8 + g][kb + tg + 4];
                asm volatile(
                    "mma.sync.aligned.m16n8k8.row.col.f32.tf32.tf32.f32 "
                    "{%0,%1,%2,%3}, {%4,%5,%6,%7}, {%8,%9}, {%0,%1,%2,%3};"
                    : "+f"(acc[nb][0]), "+f"(acc[nb][1]),
                      "+f"(acc[nb][2]), "+f"(acc[nb][3])
                    : "r"(a0), "r"(a1), "r"(a2), "r"(a3), "r"(b0), "r"(b1));
            }
        }
    }

    // epilogue: thread holds rows node0/node1, cols {nb*8 + tg*2, +1}
    const int node0 = nbase + m0 + g;
    const int node1 = node0 + 8;
    unsigned* H2 = (unsigned*)g_h;     // half2 words, 32 per node row

    float sp0 = 0.f, dp0 = 0.f, sp1 = 0.f, dp1 = 0.f;
    const float2* AS2 = (const float2*)avsrc;
    const float2* AD2 = (const float2*)avdst;
#pragma unroll
    for (int nb = 0; nb < 8; nb++) {
        float2 sv = __ldg(&AS2[nb * 4 + tg]);
        float2 dv = __ldg(&AD2[nb * 4 + tg]);
        sp0 += acc[nb][0] * sv.x + acc[nb][1] * sv.y;
        dp0 += acc[nb][0] * dv.x + acc[nb][1] * dv.y;
        sp1 += acc[nb][2] * sv.x + acc[nb][3] * sv.y;
        dp1 += acc[nb][2] * dv.x + acc[nb][3] * dv.y;
        if (node0 < N_NODES)
            H2[(long)node0 * 32 + nb * 4 + tg] = packh2(acc[nb][0], acc[nb][1]);
        if (node1 < N_NODES)
            H2[(long)node1 * 32 + nb * 4 + tg] = packh2(acc[nb][2], acc[nb][3]);
    }
    // reduce over the 4 quad threads sharing a row
#pragma unroll
    for (int m = 1; m < 4; m <<= 1) {
        sp0 += __shfl_xor_sync(FULLM, sp0, m);
        dp0 += __shfl_xor_sync(FULLM, dp0, m);
        sp1 += __shfl_xor_sync(FULLM, sp1, m);
        dp1 += __shfl_xor_sync(FULLM, dp1, m);
    }
    if (tg == 0) {
        if (node0 < N_NODES) { g_as[node0] = sp0; g_ad[node0] = dp0; }
        if (node1 < N_NODES) { g_as[node1] = sp1; g_ad[node1] = dp1; }
    }
}

// ---------------- single-kernel decoupled-lookback scan of g_deg -> g_rowptr ----------
__global__ void __launch_bounds__(1024) k_scan() {
    __shared__ int s[1024];
    __shared__ int s_prefix;
    const int t = threadIdx.x;
    const int tile = blockIdx.x;
    const int i = tile * 1024 + t;
    int v = (i <= N_NODES) ? g_deg[i] : 0;
    s[t] = v;
    __syncthreads();
    for (int off = 1; off < 1024; off <<= 1) {
        int x = (t >= off) ? s[t - off] : 0;
        __syncthreads();
        s[t] += x;
        __syncthreads();
    }
    const int inc = s[t];
    const int total = s[1023];

    if (t == 0) {
        if (tile == 0) {
            atomicExch(&g_tstat[0], (2u << 30) | (unsigned)total);
            s_prefix = 0;
        } else {
            atomicExch(&g_tstat[tile], (1u << 30) | (unsigned)total);
            int prefix = 0;
            int p = tile - 1;
            while (true) {
                unsigned st = *(volatile unsigned*)&g_tstat[p];
                unsigned f = st >> 30;
                if (f == 0u) continue;
                prefix += (int)(st & 0x3FFFFFFFu);
                if (f == 2u) break;
                p--;
            }
            atomicExch(&g_tstat[tile], (2u << 30) | (unsigned)(prefix + total));
            s_prefix = prefix;
        }
    }
    __syncthreads();
    const int val = inc + s_prefix;
    if (i <= N_NODES) g_rowptr[i] = val;
}

// ---------------- atomic-free adjacency fill + u/v precompute + cleanup -------------
// pos = rowptr[dst] + precomputed bucket rank: loads + one scattered store only.
// Block 3125 computes u = W2^T a_src2, v = W2^T a_dst2 and zeroes g_m.
__global__ void __launch_bounds__(512) k_fill(const int* __restrict__ ei,
                                              const float* __restrict__ W2,
                                              const float* __restrict__ as2v,
                                              const float* __restrict__ ad2v) {
    if (blockIdx.x == 3125) {
        int k = threadIdx.x;
        if (k < 64) {
            float u = 0.f, v = 0.f;
#pragma unroll 8
            for (int o = 0; o < 64; o++) {
                float w = __ldg(&W2[o * 64 + k]);
                u += __ldg(&as2v[o]) * w;
                v += __ldg(&ad2v[o]) * w;
            }
            g_u[k] = u;
            g_v[k] = v;
            g_m[k] = 0.f;
        }
        return;
    }
    int gid = blockIdx.x * 512 + threadIdx.x;
    if (gid <= N_NODES) g_deg[gid] = 0;       // reset for next kernel_launch call
    if (gid < NB_SCAN) g_tstat[gid] = 0u;     // reset lookback status
    if (gid < N_EDGES) {
        int d   = __ldg(&ei[N_EDGES + gid]);
        int pos = __ldg(&g_rowptr[d]) + g_ord[gid];
        g_adj[pos] = __ldg(&ei[gid]);
    }
}

// ---------------- half-warp-per-node softmax aggregation (atomic-free) ---------------
// 16 lanes own one node; lane l holds features [4l, 4l+4) as fp16 (8B/lane):
// one 128B wavefront per gathered edge row. Accumulation, logits, softmax all
// fp32. Single predicated 4-wide batch loop: invalid tail slots carry
// (s=0, ex=0) so they gather row 0 with zero weight (MLP 4 on tails).
// exp-max subtraction omitted: logits are O(10), fp32 exp cannot overflow.
// mode 1: bias+relu, store g_feat (fp16) + emit layer-2 logit halves
//         as2 = feat.u, ad2 = feat.v (replaces the layer-2 gemm by linearity).
// mode 2: pool normalized aggregate into g_m (k_fin applies W2, 1/N, b2).
__global__ void __launch_bounds__(512)
k_agg(const float* __restrict__ b, int mode) {
    __shared__ float sred[64];
    if (mode == 2) {
        if (threadIdx.x < 64) sred[threadIdx.x] = 0.f;
        __syncthreads();
    }
    const int lane = threadIdx.x & 31;
    const int l = lane & 15;
    const unsigned hm = 0xFFFFu << (lane & 16);
    const int node = (blockIdx.x * 512 + threadIdx.x) >> 4;   // exact: 3125*512/16 = 100000

    const uint2* H = (mode == 1) ? g_h : g_feat;
    const float* asp = (mode == 1) ? g_as : g_as2;
    const float* adp = (mode == 1) ? g_ad : g_ad2;

    const float adn = adp[node];
    float e0 = asp[node] + adn;
    e0 = (e0 > 0.f) ? e0 : NEG_SLOPE * e0;
    const float exs = __expf(e0);                 // self-loop term

    float4 hv = unpack4h(__ldg(H + (long)node * 16 + l));
    float4 acc = make_float4(exs * hv.x, exs * hv.y, exs * hv.z, exs * hv.w);
    float dsum = 0.f;

    const int beg = __ldg(&g_rowptr[node]);
    const int end = __ldg(&g_rowptr[node + 1]);
    for (int k = beg; k < end; k += 16) {
        int idx = k + l;
        int s = 0;
        float ex = 0.f;
        if (idx < end) {
            s = __ldg(&g_adj[idx]);
            float e = __ldg(&asp[s]) + adn;
            e = (e > 0.f) ? e : NEG_SLOPE * e;
            ex = __expf(e);
        }
        dsum += ex;
        const int cnt = min(16, end - k);
        for (int j = 0; j < cnt; j += 4) {
            int   s0 = __shfl_sync(hm, s, j, 16);
            int   s1 = __shfl_sync(hm, s, j + 1, 16);
            int   s2 = __shfl_sync(hm, s, j + 2, 16);
            int   s3 = __shfl_sync(hm, s, j + 3, 16);
            float x0 = __shfl_sync(hm, ex, j, 16);
            float x1 = __shfl_sync(hm, ex, j + 1, 16);
            float x2 = __shfl_sync(hm, ex, j + 2, 16);
            float x3 = __shfl_sync(hm, ex, j + 3, 16);
            float4 h0 = unpack4h(__ldg(H + (long)s0 * 16 + l));
            float4 h1 = unpack4h(__ldg(H + (long)s1 * 16 + l));
            float4 h2 = unpack4h(__ldg(H + (long)s2 * 16 + l));
            float4 h3 = unpack4h(__ldg(H + (long)s3 * 16 + l));
            acc.x += x0 * h0.x; acc.y += x0 * h0.y; acc.z += x0 * h0.z; acc.w += x0 * h0.w;
            acc.x += x1 * h1.x; acc.y += x1 * h1.y; acc.z += x1 * h1.z; acc.w += x1 * h1.w;
            acc.x += x2 * h2.x; acc.y += x2 * h2.y; acc.z += x2 * h2.z; acc.w += x2 * h2.w;
            acc.x += x3 * h3.x; acc.y += x3 * h3.y; acc.z += x3 * h3.z; acc.w += x3 * h3.w;
        }
    }
#pragma unroll
    for (int m = 8; m; m >>= 1) dsum += __shfl_xor_sync(hm, dsum, m, 16);

    const float inv = 1.0f / (dsum + exs);

    if (mode == 1) {
        float4 bb = __ldg((const float4*)b + l);
        float4 r = make_float4(fmaxf(acc.x * inv + bb.x, 0.f),
                               fmaxf(acc.y * inv + bb.y, 0.f),
                               fmaxf(acc.z * inv + bb.z, 0.f),
                               fmaxf(acc.w * inv + bb.w, 0.f));
        g_feat[(long)node * 16 + l] = pack4h(r.x, r.y, r.z, r.w);
        // layer-2 logit halves from the in-register (fp32) feat row
        float4 uu = __ldg((const float4*)g_u + l);
        float4 vv = __ldg((const float4*)g_v + l);
        float sp = r.x * uu.x + r.y * uu.y + r.z * uu.z + r.w * uu.w;
        float dp = r.x * vv.x + r.y * vv.y + r.z * vv.z + r.w * vv.w;
#pragma unroll
        for (int m = 8; m; m >>= 1) {
            sp += __shfl_xor_sync(hm, sp, m, 16);
            dp += __shfl_xor_sync(hm, dp, m, 16);
        }
        if (l == 0) { g_as2[node] = sp; g_ad2[node] = dp; }
    } else {
        // pool normalized aggregate (W2/b2/(1/N) applied in k_fin)
        float4 r = make_float4(acc.x * inv, acc.y * inv, acc.z * inv, acc.w * inv);
        __syncwarp(FULLM);
        r.x += __shfl_xor_sync(FULLM, r.x, 16);
        r.y += __shfl_xor_sync(FULLM, r.y, 16);
        r.z += __shfl_xor_sync(FULLM, r.z, 16);
        r.w += __shfl_xor_sync(FULLM, r.w, 16);
        if (lane < 16) {
            atomicAdd(&sred[4 * l + 0], r.x);
            atomicAdd(&sred[4 * l + 1], r.y);
            atomicAdd(&sred[4 * l + 2], r.z);
            atomicAdd(&sred[4 * l + 3], r.w);
        }
        __syncthreads();
        if (threadIdx.x < 64)
            atomicAdd(&g_m[threadIdx.x], sred[threadIdx.x]);
    }
}

// ---------------- final projection: out = W2 (g_m / N) + b2 ----------------
__global__ void k_fin(const float* __restrict__ W2,
                      const float* __restrict__ b2,
                      float* __restrict__ out) {
    int o = threadIdx.x;
    float s = 0.f;
#pragma unroll 8
    for (int k = 0; k < 64; k++)
        s += __ldg(&W2[o * 64 + k]) * g_m[k];
    out[o] = s * (1.0f / N_NODES) + __ldg(&b2[o]);
}

// ---------------- launch ----------------
extern "C" void kernel_launch(void* const* d_in, const int* in_sizes, int n_in,
                              void* d_out, int out_size) {
    const float* x   = (const float*)d_in[0];
    const int*   ei  = (const int*)d_in[1];
    // d_in[2] = edge_attr (unused; GATConv edge_dim=None)
    const float* W1  = (const float*)d_in[3];
    const float* as1 = (const float*)d_in[4];
    const float* ad1 = (const float*)d_in[5];
    const float* b1  = (const float*)d_in[6];
    const float* W2  = (const float*)d_in[7];
    const float* as2 = (const float*)d_in[8];
    const float* ad2 = (const float*)d_in[9];
    const float* b2  = (const float*)d_in[10];
    float* out = (float*)d_out;

    // (0) layer-1 tf32 mma gemm + dst histogram/rank capture (fused)
    k_gemm1<<<GB_G1 + GB_HIST, 256>>>(x, W1, as1, ad1, ei);
    // (1) rowptr via single-kernel decoupled lookback scan
    k_scan<<<NB_SCAN, 1024>>>();
    // (2) atomic-free adjacency fill + u/v vectors + scratch reset
    k_fill<<<3126, 512>>>(ei, W2, as2, ad2);
    // (3) layer-1 aggregation (also emits layer-2 logit halves)
    k_agg<<<3125, 512>>>(b1, 1);
    // (4) layer-2 aggregation -> pooled mean vector g_m
    k_agg<<<3125, 512>>>(nullptr, 2);
    // (5) out = W2 (g_m/N) + b2
    k_fin<<<1, 64>>>(W2, b2, out);
}

// round 14
// speedup vs baseline: 1.8173x; 1.0584x over previous
#include <cuda_runtime.h>
#include <cuda_fp16.h>

#define N_NODES 100000
#define N_EDGES 1600000
#define NB_SCAN 98              // ceil((N_NODES+1)/1024)
#define NEG_SLOPE 0.2f
#define FULLM 0xffffffffu
#define GB_G1 782               // ceil(N_NODES/128) gemm tiles
#define GB_HIST 6250            // ceil(N_EDGES/256)

// ---------------- scratch (device globals; zero-initialized at module load) ----------
// Cross-call invariant: g_deg and g_tstat are zero at the start of every
// kernel_launch call — module-load zero-init covers the first call; k_fill
// re-zeroes them (after their last use) for every later call. g_m is zeroed
// by k_fill each call before agg2 accumulates into it.
__device__ int      g_deg[N_NODES + 1];
__device__ int      g_rowptr[N_NODES + 1];
__device__ int      g_ord[N_EDGES];       // within-dst-bucket rank of each edge
__device__ unsigned g_tstat[NB_SCAN];     // lookback status: [31:30] flag (1=agg,2=prefix), [29:0] value
__device__ int      g_adj[N_EDGES];       // src indices in CSR (dst-grouped) order
__device__ uint2    g_h[N_NODES * 16];    // layer-1 features, fp16 rows (64 x half = 128B/row)
__device__ uint2    g_feat[N_NODES * 16]; // layer-1 output, fp16 rows (layer-2 gather source)
__device__ float    g_as[N_NODES];        // layer-1 logit halves (fp32)
__device__ float    g_ad[N_NODES];
__device__ float    g_as2[N_NODES];       // layer-2 logit halves (feat . u / feat . v)
__device__ float    g_ad2[N_NODES];
__device__ float    g_u[64];              // u = W2^T a_src2
__device__ float    g_v[64];              // v = W2^T a_dst2
__device__ float    g_m[64];              // softmax-weighted feat aggregate (sum over nodes)

__device__ __forceinline__ uint2 pack4h(float a, float b, float c, float d) {
    __half2 p0 = __floats2half2_rn(a, b);
    __half2 p1 = __floats2half2_rn(c, d);
    uint2 r;
    r.x = *reinterpret_cast<unsigned*>(&p0);
    r.y = *reinterpret_cast<unsigned*>(&p1);
    return r;
}
__device__ __forceinline__ float4 unpack4h(uint2 v) {
    float2 f0 = __half22float2(*reinterpret_cast<__half2*>(&v.x));
    float2 f1 = __half22float2(*reinterpret_cast<__half2*>(&v.y));
    return make_float4(f0.x, f0.y, f1.x, f1.y);
}
__device__ __forceinline__ unsigned tf32b(float f) {
    unsigned r;
    asm("cvt.rna.tf32.f32 %0, %1;" : "=r"(r) : "f"(f));
    return r;
}
__device__ __forceinline__ unsigned packh2(float a, float b) {
    __half2 p = __floats2half2_rn(a, b);
    return *reinterpret_cast<unsigned*>(&p);
}
__device__ __forceinline__ __half2 u2h2(unsigned u) {
    return *reinterpret_cast<__half2*>(&u);
}

// ---------------- tf32 mma.sync GEMM (h = X @ W1^T) + attention logits ---------------
// Block = 256 threads = 8 warps; tile 128 nodes x 64 outs. Warp w owns rows
// w*16..+15; per warp 8 n-blocks of m16n8k8 tf32 mma (fp32 accumulate).
// K staged 16 at a time into smem (tf32-converted), row stride 20 words:
// all A/B fragment LDS patterns are bank-conflict-free. Logits reduced
// in-warp over the 4 quad threads. h written as fp16 rows (agg layout).
// HIST blocks (>= GB_G1) run the dst-degree histogram + bucket-rank capture;
// the atomicAdd return value IS the edge's rank -> k_fill needs no atomics.
__global__ void __launch_bounds__(256)
k_gemm1(const float* __restrict__ X,
        const float* __restrict__ W,
        const float* __restrict__ avsrc,
        const float* __restrict__ avdst,
        const int* __restrict__ ei) {
    if (blockIdx.x >= GB_G1) {
        int e = (blockIdx.x - GB_G1) * 256 + threadIdx.x;
        if (e < N_EDGES) {
            int d = __ldg(&ei[N_EDGES + e]);
            g_ord[e] = atomicAdd(&g_deg[d + 1], 1);
        }
        return;
    }
    __shared__ unsigned xs[128][20];   // X chunk, tf32 bits, [row][k0..15], stride 20
    __shared__ unsigned ws[64][20];    // W chunk, tf32 bits, [out][k0..15]

    const int tid  = threadIdx.x;
    const int lane = tid & 31;
    const int wid  = tid >> 5;         // warp 0..7
    const int g    = lane >> 2;        // groupID (row-in-16 / col-in-8)
    const int tg   = lane & 3;         // threadID_in_group
    const int nbase = blockIdx.x * 128;
    const int m0 = wid * 16;

    const float4* X4 = (const float4*)X;   // 32 float4 per 128-float row
    const float4* W4 = (const float4*)W;

    float acc[8][4];
#pragma unroll
    for (int nb = 0; nb < 8; nb++)
#pragma unroll
        for (int i = 0; i < 4; i++) acc[nb][i] = 0.f;

#pragma unroll 1
    for (int ch = 0; ch < 8; ch++) {
        __syncthreads();
        // stage X chunk: 128 rows x 16 k (512 float4, 2 per thread)
#pragma unroll
        for (int it = 0; it < 2; it++) {
            int idx = tid + it * 256;
            int r  = idx >> 2;
            int c4 = idx & 3;
            int xrow = min(nbase + r, N_NODES - 1);        // clamp tail (stores guarded)
            float4 v = __ldg(&X4[(long)xrow * 32 + ch * 4 + c4]);
            *(uint4*)&xs[r][c4 * 4] =
                make_uint4(tf32b(v.x), tf32b(v.y), tf32b(v.z), tf32b(v.w));
        }
        // stage W chunk: 64 rows x 16 k (256 float4, 1 per thread)
        {
            int r  = tid >> 2;
            int c4 = tid & 3;
            float4 v = __ldg(&W4[(long)r * 32 + ch * 4 + c4]);
            *(uint4*)&ws[r][c4 * 4] =
                make_uint4(tf32b(v.x), tf32b(v.y), tf32b(v.z), tf32b(v.w));
        }
        __syncthreads();

#pragma unroll
        for (int ks = 0; ks < 2; ks++) {
            const int kb = ks * 8;
            unsigned a0 = xs[m0 + g][kb + tg];
            unsigned a1 = xs[m0 + g + 8][kb + tg];
            unsigned a2 = xs[m0 + g][kb + tg + 4];
            unsigned a3 = xs[m0 + g + 8][kb + tg + 4];
#pragma unroll
            for (int nb = 0; nb < 8; nb++) {
                unsigned b0 = ws[nb * 8 + g][kb + tg];
                unsigned b1 = ws[nb * 8 + g][kb + tg + 4];
                asm volatile(
                    "mma.sync.aligned.m16n8k8.row.col.f32.tf32.tf32.f32 "
                    "{%0,%1,%2,%3}, {%4,%5,%6,%7}, {%8,%9}, {%0,%1,%2,%3};"
                    : "+f"(acc[nb][0]), "+f"(acc[nb][1]),
                      "+f"(acc[nb][2]), "+f"(acc[nb][3])
                    : "r"(a0), "r"(a1), "r"(a2), "r"(a3), "r"(b0), "r"(b1));
            }
        }
    }

    // epilogue: thread holds rows node0/node1, cols {nb*8 + tg*2, +1}
    const int node0 = nbase + m0 + g;
    const int node1 = node0 + 8;
    unsigned* H2 = (unsigned*)g_h;     // half2 words, 32 per node row

    float sp0 = 0.f, dp0 = 0.f, sp1 = 0.f, dp1 = 0.f;
    const float2* AS2 = (const float2*)avsrc;
    const float2* AD2 = (const float2*)avdst;
#pragma unroll
    for (int nb = 0; nb < 8; nb++) {
        float2 sv = __ldg(&AS2[nb * 4 + tg]);
        float2 dv = __ldg(&AD2[nb * 4 + tg]);
        sp0 += acc[nb][0] * sv.x + acc[nb][1] * sv.y;
        dp0 += acc[nb][0] * dv.x + acc[nb][1] * dv.y;
        sp1 += acc[nb][2] * sv.x + acc[nb][3] * sv.y;
        dp1 += acc[nb][2] * dv.x + acc[nb][3] * dv.y;
        if (node0 < N_NODES)
            H2[(long)node0 * 32 + nb * 4 + tg] = packh2(acc[nb][0], acc[nb][1]);
        if (node1 < N_NODES)
            H2[(long)node1 * 32 + nb * 4 + tg] = packh2(acc[nb][2], acc[nb][3]);
    }
    // reduce over the 4 quad threads sharing a row
#pragma unroll
    for (int m = 1; m < 4; m <<= 1) {
        sp0 += __shfl_xor_sync(FULLM, sp0, m);
        dp0 += __shfl_xor_sync(FULLM, dp0, m);
        sp1 += __shfl_xor_sync(FULLM, sp1, m);
        dp1 += __shfl_xor_sync(FULLM, dp1, m);
    }
    if (tg == 0) {
        if (node0 < N_NODES) { g_as[node0] = sp0; g_ad[node0] = dp0; }
        if (node1 < N_NODES) { g_as[node1] = sp1; g_ad[node1] = dp1; }
    }
}

// ---------------- single-kernel decoupled-lookback scan of g_deg -> g_rowptr ----------
__global__ void __launch_bounds__(1024) k_scan() {
    __shared__ int s[1024];
    __shared__ int s_prefix;
    const int t = threadIdx.x;
    const int tile = blockIdx.x;
    const int i = tile * 1024 + t;
    int v = (i <= N_NODES) ? g_deg[i] : 0;
    s[t] = v;
    __syncthreads();
    for (int off = 1; off < 1024; off <<= 1) {
        int x = (t >= off) ? s[t - off] : 0;
        __syncthreads();
        s[t] += x;
        __syncthreads();
    }
    const int inc = s[t];
    const int total = s[1023];

    if (t == 0) {
        if (tile == 0) {
            atomicExch(&g_tstat[0], (2u << 30) | (unsigned)total);
            s_prefix = 0;
        } else {
            atomicExch(&g_tstat[tile], (1u << 30) | (unsigned)total);
            int prefix = 0;
            int p = tile - 1;
            while (true) {
                unsigned st = *(volatile unsigned*)&g_tstat[p];
                unsigned f = st >> 30;
                if (f == 0u) continue;
                prefix += (int)(st & 0x3FFFFFFFu);
                if (f == 2u) break;
                p--;
            }
            atomicExch(&g_tstat[tile], (2u << 30) | (unsigned)(prefix + total));
            s_prefix = prefix;
        }
    }
    __syncthreads();
    const int val = inc + s_prefix;
    if (i <= N_NODES) g_rowptr[i] = val;
}

// ---------------- atomic-free adjacency fill + u/v precompute + cleanup -------------
// pos = rowptr[dst] + precomputed bucket rank: loads + one scattered store only.
// Block 3125 computes u = W2^T a_src2, v = W2^T a_dst2 and zeroes g_m.
__global__ void __launch_bounds__(512) k_fill(const int* __restrict__ ei,
                                              const float* __restrict__ W2,
                                              const float* __restrict__ as2v,
                                              const float* __restrict__ ad2v) {
    if (blockIdx.x == 3125) {
        int k = threadIdx.x;
        if (k < 64) {
            float u = 0.f, v = 0.f;
#pragma unroll 8
            for (int o = 0; o < 64; o++) {
                float w = __ldg(&W2[o * 64 + k]);
                u += __ldg(&as2v[o]) * w;
                v += __ldg(&ad2v[o]) * w;
            }
            g_u[k] = u;
            g_v[k] = v;
            g_m[k] = 0.f;
        }
        return;
    }
    int gid = blockIdx.x * 512 + threadIdx.x;
    if (gid <= N_NODES) g_deg[gid] = 0;       // reset for next kernel_launch call
    if (gid < NB_SCAN) g_tstat[gid] = 0u;     // reset lookback status
    if (gid < N_EDGES) {
        int d   = __ldg(&ei[N_EDGES + gid]);
        int pos = __ldg(&g_rowptr[d]) + g_ord[gid];
        g_adj[pos] = __ldg(&ei[gid]);
    }
}

// ---------------- half-warp-per-node softmax aggregation (atomic-free) ---------------
// 16 lanes own one node; lane l holds features [4l, 4l+4) as fp16 (8B/lane):
// one 128B wavefront per gathered edge row. NEW: accumulation in fp16 via
// HFMA2 — the per-chunk edge weight is converted ONCE per lane to a broadcast
// half2 (scaled by 1/16, exact in fp16, restored x16 in fp32 after the loop;
// overflow would need sum(ex*|h|) > 1e6, an ~8-sigma event for N(0,2) logits)
// and shfl'd as raw bits. Per-4-edge body: 8 shfl + 4 LDG + 8 HFMA2 (was 36
// issue slots with fp32 unpack+FFMA). dsum, softmax normalize, logits, bias
// all stay fp32. Single predicated 4-wide batch loop: invalid tail slots
// carry (s=0, exh=0) so they gather row 0 with zero weight.
// mode 1: bias+relu, store g_feat (fp16) + emit layer-2 logit halves
//         as2 = feat.u, ad2 = feat.v (replaces the layer-2 gemm by linearity).
// mode 2: pool normalized aggregate into g_m (k_fin applies W2, 1/N, b2).
__global__ void __launch_bounds__(512)
k_agg(const float* __restrict__ b, int mode) {
    __shared__ float sred[64];
    if (mode == 2) {
        if (threadIdx.x < 64) sred[threadIdx.x] = 0.f;
        __syncthreads();
    }
    const int lane = threadIdx.x & 31;
    const int l = lane & 15;
    const unsigned hm = 0xFFFFu << (lane & 16);
    const int node = (blockIdx.x * 512 + threadIdx.x) >> 4;   // exact: 3125*512/16 = 100000

    const uint2* H = (mode == 1) ? g_h : g_feat;
    const float* asp = (mode == 1) ? g_as : g_as2;
    const float* adp = (mode == 1) ? g_ad : g_ad2;

    const float adn = adp[node];
    float e0 = asp[node] + adn;
    e0 = (e0 > 0.f) ? e0 : NEG_SLOPE * e0;
    const float exs = __expf(e0);                 // self-loop term (fp32 for denom)

    uint2 hrow = __ldg(H + (long)node * 16 + l);
    __half2 es2 = __float2half2_rn(exs * 0.0625f);
    __half2 hacc0 = __hmul2(es2, u2h2(hrow.x));
    __half2 hacc1 = __hmul2(es2, u2h2(hrow.y));
    float dsum = 0.f;

    const int beg = __ldg(&g_rowptr[node]);
    const int end = __ldg(&g_rowptr[node + 1]);
    for (int k = beg; k < end; k += 16) {
        int idx = k + l;
        int s = 0;
        unsigned exh = 0u;                        // half2(0,0)
        if (idx < end) {
            s = __ldg(&g_adj[idx]);
            float e = __ldg(&asp[s]) + adn;
            e = (e > 0.f) ? e : NEG_SLOPE * e;
            float ex = __expf(e);
            dsum += ex;
            __half2 t = __float2half2_rn(ex * 0.0625f);
            exh = *reinterpret_cast<unsigned*>(&t);
        }
        const int cnt = min(16, end - k);
        for (int j = 0; j < cnt; j += 4) {
            int      s0 = __shfl_sync(hm, s, j, 16);
            int      s1 = __shfl_sync(hm, s, j + 1, 16);
            int      s2 = __shfl_sync(hm, s, j + 2, 16);
            int      s3 = __shfl_sync(hm, s, j + 3, 16);
            unsigned e0b = __shfl_sync(hm, exh, j, 16);
            unsigned e1b = __shfl_sync(hm, exh, j + 1, 16);
            unsigned e2b = __shfl_sync(hm, exh, j + 2, 16);
            unsigned e3b = __shfl_sync(hm, exh, j + 3, 16);
            uint2 h0 = __ldg(H + (long)s0 * 16 + l);
            uint2 h1 = __ldg(H + (long)s1 * 16 + l);
            uint2 h2 = __ldg(H + (long)s2 * 16 + l);
            uint2 h3 = __ldg(H + (long)s3 * 16 + l);
            hacc0 = __hfma2(u2h2(e0b), u2h2(h0.x), hacc0);
            hacc1 = __hfma2(u2h2(e0b), u2h2(h0.y), hacc1);
            hacc0 = __hfma2(u2h2(e1b), u2h2(h1.x), hacc0);
            hacc1 = __hfma2(u2h2(e1b), u2h2(h1.y), hacc1);
            hacc0 = __hfma2(u2h2(e2b), u2h2(h2.x), hacc0);
            hacc1 = __hfma2(u2h2(e2b), u2h2(h2.y), hacc1);
            hacc0 = __hfma2(u2h2(e3b), u2h2(h3.x), hacc0);
            hacc1 = __hfma2(u2h2(e3b), u2h2(h3.y), hacc1);
        }
    }
#pragma unroll
    for (int m = 8; m; m >>= 1) dsum += __shfl_xor_sync(hm, dsum, m, 16);

    // restore scale (x16) and normalize in fp32
    float2 f0 = __half22float2(hacc0);
    float2 f1 = __half22float2(hacc1);
    const float inv = 16.0f / (dsum + exs);
    float4 acc = make_float4(f0.x * inv, f0.y * inv, f1.x * inv, f1.y * inv);

    if (mode == 1) {
        float4 bb = __ldg((const float4*)b + l);
        float4 r = make_float4(fmaxf(acc.x + bb.x, 0.f),
                               fmaxf(acc.y + bb.y, 0.f),
                               fmaxf(acc.z + bb.z, 0.f),
                               fmaxf(acc.w + bb.w, 0.f));
        g_feat[(long)node * 16 + l] = pack4h(r.x, r.y, r.z, r.w);
        // layer-2 logit halves from the in-register (fp32) feat row
        float4 uu = __ldg((const float4*)g_u + l);
        float4 vv = __ldg((const float4*)g_v + l);
        float sp = r.x * uu.x + r.y * uu.y + r.z * uu.z + r.w * uu.w;
        float dp = r.x * vv.x + r.y * vv.y + r.z * vv.z + r.w * vv.w;
#pragma unroll
        for (int m = 8; m; m >>= 1) {
            sp += __shfl_xor_sync(hm, sp, m, 16);
            dp += __shfl_xor_sync(hm, dp, m, 16);
        }
        if (l == 0) { g_as2[node] = sp; g_ad2[node] = dp; }
    } else {
        // pool normalized aggregate (W2/b2/(1/N) applied in k_fin)
        __syncwarp(FULLM);
        acc.x += __shfl_xor_sync(FULLM, acc.x, 16);
        acc.y += __shfl_xor_sync(FULLM, acc.y, 16);
        acc.z += __shfl_xor_sync(FULLM, acc.z, 16);
        acc.w += __shfl_xor_sync(FULLM, acc.w, 16);
        if (lane < 16) {
            atomicAdd(&sred[4 * l + 0], acc.x);
            atomicAdd(&sred[4 * l + 1], acc.y);
            atomicAdd(&sred[4 * l + 2], acc.z);
            atomicAdd(&sred[4 * l + 3], acc.w);
        }
        __syncthreads();
        if (threadIdx.x < 64)
            atomicAdd(&g_m[threadIdx.x], sred[threadIdx.x]);
    }
}

// ---------------- final projection: out = W2 (g_m / N) + b2 ----------------
__global__ void k_fin(const float* __restrict__ W2,
                      const float* __restrict__ b2,
                      float* __restrict__ out) {
    int o = threadIdx.x;
    float s = 0.f;
#pragma unroll 8
    for (int k = 0; k < 64; k++)
        s += __ldg(&W2[o * 64 + k]) * g_m[k];
    out[o] = s * (1.0f / N_NODES) + __ldg(&b2[o]);
}

// ---------------- launch ----------------
extern "C" void kernel_launch(void* const* d_in, const int* in_sizes, int n_in,
                              void* d_out, int out_size) {
    const float* x   = (const float*)d_in[0];
    const int*   ei  = (const int*)d_in[1];
    // d_in[2] = edge_attr (unused; GATConv edge_dim=None)
    const float* W1  = (const float*)d_in[3];
    const float* as1 = (const float*)d_in[4];
    const float* ad1 = (const float*)d_in[5];
    const float* b1  = (const float*)d_in[6];
    const float* W2  = (const float*)d_in[7];
    const float* as2 = (const float*)d_in[8];
    const float* ad2 = (const float*)d_in[9];
    const float* b2  = (const float*)d_in[10];
    float* out = (float*)d_out;

    // (0) layer-1 tf32 mma gemm + dst histogram/rank capture (fused)
    k_gemm1<<<GB_G1 + GB_HIST, 256>>>(x, W1, as1, ad1, ei);
    // (1) rowptr via single-kernel decoupled lookback scan
    k_scan<<<NB_SCAN, 1024>>>();
    // (2) atomic-free adjacency fill + u/v vectors + scratch reset
    k_fill<<<3126, 512>>>(ei, W2, as2, ad2);
    // (3) layer-1 aggregation (also emits layer-2 logit halves)
    k_agg<<<3125, 512>>>(b1, 1);
    // (4) layer-2 aggregation -> pooled mean vector g_m
    k_agg<<<3125, 512>>>(nullptr, 2);
    // (5) out = W2 (g_m/N) + b2
    k_fin<<<1, 64>>>(W2, b2, out);
}